// round 4
// baseline (speedup 1.0000x reference)
#include <cuda_runtime.h>
#include <math.h>

// Problem constants (fixed by the reference).
#define B_ 2
#define S_ 2048
#define D_ 1024
#define H_ 16
#define DK_ 64
#define M_ (B_ * S_)   // 4096 token rows

// Scratch (allocation-free rule: __device__ globals).
__device__ float g_q[B_ * H_ * S_ * DK_];     // [b,h,s,d]
__device__ float g_k[B_ * H_ * S_ * DK_];
__device__ float g_v[B_ * H_ * S_ * DK_];
__device__ float g_attn[M_ * D_];             // [b,s,h*dk]

// ---------------------------------------------------------------------------
// tf32 / cp.async helpers
// ---------------------------------------------------------------------------
__device__ __forceinline__ unsigned f2tf32(float f) {
    unsigned u;
    asm("cvt.rna.tf32.f32 %0, %1;" : "=r"(u) : "f"(f));
    return u;
}

__device__ __forceinline__ void mma_tf32(float (&c)[4], const unsigned (&a)[4],
                                         const unsigned (&b)[2]) {
    asm volatile(
        "mma.sync.aligned.m16n8k8.row.col.f32.tf32.tf32.f32 "
        "{%0,%1,%2,%3}, {%4,%5,%6,%7}, {%8,%9}, {%0,%1,%2,%3};\n"
        : "+f"(c[0]), "+f"(c[1]), "+f"(c[2]), "+f"(c[3])
        : "r"(a[0]), "r"(a[1]), "r"(a[2]), "r"(a[3]), "r"(b[0]), "r"(b[1]));
}

__device__ __forceinline__ void cp_async16(void* smem, const void* gmem) {
    unsigned saddr = (unsigned)__cvta_generic_to_shared(smem);
    asm volatile("cp.async.cg.shared.global [%0], [%1], 16;\n" ::"r"(saddr),
                 "l"(gmem));
}
__device__ __forceinline__ void cp_commit() {
    asm volatile("cp.async.commit_group;\n");
}
template <int N>
__device__ __forceinline__ void cp_wait() {
    asm volatile("cp.async.wait_group %0;\n" ::"n"(N));
}

// ---------------------------------------------------------------------------
// tf32 GEMM body (NT): C[m,n] = sum_k A[m,k] * W[n,k].
// Tile 128x128, BK=32, 256 threads, 8 warps, warp tile 64x32.
// MODE 0: plain write, MODE 1: [b,h,s,d] scatter, MODE 2: scatter + RoPE
// ---------------------------------------------------------------------------
#define GSTRIDE 36
#define GEMM_SMEM (2 * 2 * 128 * GSTRIDE * 4)

template <int MODE>
__device__ __forceinline__ void gemm_body(
    float* sm, const float* __restrict__ A, const float* __restrict__ W,
    float* __restrict__ Cout, const int* __restrict__ pos) {
    float(*As)[128][GSTRIDE] = reinterpret_cast<float(*)[128][GSTRIDE]>(sm);
    float(*Bs)[128][GSTRIDE] =
        reinterpret_cast<float(*)[128][GSTRIDE]>(sm + 2 * 128 * GSTRIDE);

    const int tid = threadIdx.x;
    const int lane = tid & 31;
    const int warp = tid >> 5;
    const int wr = warp >> 2;
    const int wc = warp & 3;
    const int m0 = blockIdx.y * 128;
    const int n0 = blockIdx.x * 128;
    const int gid = lane >> 2;
    const int tig = lane & 3;

    const float* Ab = A + (size_t)m0 * D_;
    const float* Wb = W + (size_t)n0 * D_;

    float acc[4][4][4];
#pragma unroll
    for (int i = 0; i < 4; ++i)
#pragma unroll
        for (int j = 0; j < 4; ++j)
#pragma unroll
            for (int r = 0; r < 4; ++r) acc[i][j][r] = 0.0f;

    auto issue = [&](int buf, int k0) {
#pragma unroll
        for (int i = 0; i < 4; ++i) {
            int l = tid + i * 256;
            int r = l >> 3;
            int c = (l & 7) << 2;
            cp_async16(&As[buf][r][c], Ab + (size_t)r * D_ + k0 + c);
            cp_async16(&Bs[buf][r][c], Wb + (size_t)r * D_ + k0 + c);
        }
        cp_commit();
    };

    const int NIT = D_ / 32;
    issue(0, 0);
    int buf = 0;
    for (int it = 0; it < NIT; ++it) {
        if (it + 1 < NIT) {
            issue(buf ^ 1, (it + 1) * 32);
            cp_wait<1>();
        } else {
            cp_wait<0>();
        }
        __syncthreads();

#pragma unroll
        for (int kk = 0; kk < 32; kk += 8) {
            unsigned af[4][4], bf[4][2];
#pragma unroll
            for (int mt = 0; mt < 4; ++mt) {
                int r = wr * 64 + mt * 16 + gid;
                af[mt][0] = f2tf32(As[buf][r][kk + tig]);
                af[mt][1] = f2tf32(As[buf][r + 8][kk + tig]);
                af[mt][2] = f2tf32(As[buf][r][kk + tig + 4]);
                af[mt][3] = f2tf32(As[buf][r + 8][kk + tig + 4]);
            }
#pragma unroll
            for (int nt = 0; nt < 4; ++nt) {
                int rn = wc * 32 + nt * 8 + gid;
                bf[nt][0] = f2tf32(Bs[buf][rn][kk + tig]);
                bf[nt][1] = f2tf32(Bs[buf][rn][kk + tig + 4]);
            }
#pragma unroll
            for (int mt = 0; mt < 4; ++mt)
#pragma unroll
                for (int nt = 0; nt < 4; ++nt) mma_tf32(acc[mt][nt], af[mt], bf[nt]);
        }
        __syncthreads();
        buf ^= 1;
    }

#pragma unroll
    for (int mt = 0; mt < 4; ++mt) {
        int row0 = m0 + wr * 64 + mt * 16 + gid;
        int b0i = row0 >> 11, s0i = row0 & (S_ - 1);
        int row1 = row0 + 8;
        int b1i = row1 >> 11, s1i = row1 & (S_ - 1);

        float p0 = 0.f, p1 = 0.f;
        if (MODE == 2) {
            p0 = (float)pos[b0i * S_ + s0i];
            p1 = (float)pos[b1i * S_ + s1i];
        }

#pragma unroll
        for (int nt = 0; nt < 4; ++nt) {
            int col = n0 + wc * 32 + nt * 8 + 2 * tig;
            float e0 = acc[mt][nt][0], o0 = acc[mt][nt][1];
            float e1 = acc[mt][nt][2], o1 = acc[mt][nt][3];

            if (MODE == 2) {
                int j = (col & 63) >> 1;
                float freq = powf(10000.0f, -((float)(2 * j) / 64.0f));
                {
                    float ang = p0 * freq;
                    float cv = (float)cos((double)ang);
                    float sv = (float)sin((double)ang);
                    float re = e0 * cv - o0 * sv;
                    float ro = e0 * sv + o0 * cv;
                    e0 = re; o0 = ro;
                }
                {
                    float ang = p1 * freq;
                    float cv = (float)cos((double)ang);
                    float sv = (float)sin((double)ang);
                    float re = e1 * cv - o1 * sv;
                    float ro = e1 * sv + o1 * cv;
                    e1 = re; o1 = ro;
                }
            }

            if (MODE == 0) {
                *reinterpret_cast<float2*>(Cout + (size_t)row0 * D_ + col) =
                    make_float2(e0, o0);
                *reinterpret_cast<float2*>(Cout + (size_t)row1 * D_ + col) =
                    make_float2(e1, o1);
            } else {
                int h = col >> 6;
                int d = col & 63;
                *reinterpret_cast<float2*>(
                    Cout + (((size_t)(b0i * H_ + h) * S_ + s0i) * DK_ + d)) =
                    make_float2(e0, o0);
                *reinterpret_cast<float2*>(
                    Cout + (((size_t)(b1i * H_ + h) * S_ + s1i) * DK_ + d)) =
                    make_float2(e1, o1);
            }
        }
    }
}

// Merged Q/K/V projection: blockIdx.z selects weight + destination + mode.
__global__ void __launch_bounds__(256) gemm_qkv_kernel(
    const float* __restrict__ x, const float* __restrict__ wq,
    const float* __restrict__ wk, const float* __restrict__ wv,
    float* __restrict__ qp, float* __restrict__ kp, float* __restrict__ vp,
    const int* __restrict__ pos) {
    extern __shared__ float sm[];
    const int z = blockIdx.z;
    if (z == 0)      gemm_body<2>(sm, x, wq, qp, pos);
    else if (z == 1) gemm_body<2>(sm, x, wk, kp, pos);
    else             gemm_body<1>(sm, x, wv, vp, pos);
}

// Output projection.
__global__ void __launch_bounds__(256) gemm_out_kernel(
    const float* __restrict__ A, const float* __restrict__ W,
    float* __restrict__ Cout) {
    extern __shared__ float sm[];
    gemm_body<0>(sm, A, W, Cout, nullptr);
}

// ---------------------------------------------------------------------------
// Flash attention, tf32 tensor cores, causal.
// BM=128, BN=64, dk=64, 256 threads = 8 warps x 16 q-rows.
// Smem (104 KB -> 2 CTAs/SM):
//   Qs[128][68]   Q tile, PRE-CONVERTED tf32 bits (scaled by 1/8)
//   Ks[2][64][68] K tiles: cp.async raw fp32, converted in place per tile
//   Vs[2][64][72] V tiles: same
// P never goes to smem: S-fragment -> A-fragment via register shfl transpose.
// ---------------------------------------------------------------------------
#define FP 68
#define VP 72
#define FLASH_SMEM ((128 * FP + 2 * 64 * FP + 2 * 64 * VP) * 4)

__global__ void __launch_bounds__(256, 2) flash_tf32_kernel() {
    extern __shared__ float smf[];
    float* Qs = smf;                            // [128][FP] (tf32 bits)
    float* Ks = Qs + 128 * FP;                  // [2][64][FP]
    float* Vs = Ks + 2 * 64 * FP;               // [2][64][VP]
    unsigned* Qu = reinterpret_cast<unsigned*>(Qs);

    const int qb = gridDim.x - 1 - blockIdx.x;  // long blocks first
    const int bh = blockIdx.y;
    const int b = bh >> 4;
    const int h = bh & 15;

    const float* Qp = g_q + (size_t)bh * S_ * DK_;
    const float* Kp = g_k + (size_t)bh * S_ * DK_;
    const float* Vp = g_v + (size_t)bh * S_ * DK_;

    const int tid = threadIdx.x;
    const int lane = tid & 31;
    const int warp = tid >> 5;
    const int gid = lane >> 2;
    const int tig = lane & 3;
    const int q0 = qb * 128;
    const int mrow = warp * 16 + gid;

    // Load Q tile: scale by 1/sqrt(dk) and convert to tf32 bits once.
#pragma unroll
    for (int i = 0; i < 8; ++i) {
        int l = tid + i * 256;
        int r = l >> 4;
        int c = (l & 15) << 2;
        float4 v = *reinterpret_cast<const float4*>(Qp + (size_t)(q0 + r) * DK_ + c);
        Qu[r * FP + c + 0] = f2tf32(v.x * 0.125f);
        Qu[r * FP + c + 1] = f2tf32(v.y * 0.125f);
        Qu[r * FP + c + 2] = f2tf32(v.z * 0.125f);
        Qu[r * FP + c + 3] = f2tf32(v.w * 0.125f);
    }

    auto issueKV = [&](int bf, int k0) {
#pragma unroll
        for (int i = 0; i < 4; ++i) {
            int l = tid + i * 256;
            int r = l >> 4;
            int c = (l & 15) << 2;
            cp_async16(Ks + bf * 64 * FP + r * FP + c,
                       Kp + (size_t)(k0 + r) * DK_ + c);
            cp_async16(Vs + bf * 64 * VP + r * VP + c,
                       Vp + (size_t)(k0 + r) * DK_ + c);
        }
        cp_commit();
    };

    issueKV(0, 0);

    float m_i[2] = {-1e30f, -1e30f};
    float l_i[2] = {0.f, 0.f};
    float Oacc[8][4];
#pragma unroll
    for (int nt = 0; nt < 8; ++nt)
#pragma unroll
        for (int r = 0; r < 4; ++r) Oacc[nt][r] = 0.0f;

    const int ntiles = 2 * qb + 2;
    int buf = 0;
    for (int kb = 0; kb < ntiles; ++kb) {
        const int k0 = kb * 64;
        cp_wait<0>();
        __syncthreads();                        // tile arrived; prev reads done
        if (kb + 1 < ntiles) issueKV(buf ^ 1, k0 + 64);

        // In-place fp32 -> tf32 conversion of this K/V tile (once per tile).
        unsigned* Kb = reinterpret_cast<unsigned*>(Ks + buf * 64 * FP);
        unsigned* Vb = reinterpret_cast<unsigned*>(Vs + buf * 64 * VP);
#pragma unroll
        for (int i = 0; i < 16; ++i) {
            int idx = tid + i * 256;
            int r = idx >> 6;
            int c = idx & 63;
            Kb[r * FP + c] = f2tf32(__uint_as_float(Kb[r * FP + c]));
            Vb[r * VP + c] = f2tf32(__uint_as_float(Vb[r * VP + c]));
        }
        __syncthreads();

        // ---- S = Q K^T ----
        float Sacc[8][4];
#pragma unroll
        for (int nt = 0; nt < 8; ++nt)
#pragma unroll
            for (int r = 0; r < 4; ++r) Sacc[nt][r] = 0.0f;

#pragma unroll
        for (int kk = 0; kk < 64; kk += 8) {
            unsigned af[4];
            af[0] = Qu[(mrow) * FP + kk + tig];
            af[1] = Qu[(mrow + 8) * FP + kk + tig];
            af[2] = Qu[(mrow) * FP + kk + tig + 4];
            af[3] = Qu[(mrow + 8) * FP + kk + tig + 4];
#pragma unroll
            for (int nt = 0; nt < 8; ++nt) {
                unsigned bf[2];
                bf[0] = Kb[(nt * 8 + gid) * FP + kk + tig];
                bf[1] = Kb[(nt * 8 + gid) * FP + kk + tig + 4];
                mma_tf32(Sacc[nt], af, bf);
            }
        }

        // ---- causal mask ----
        const int row0 = q0 + mrow;
        const int row1 = row0 + 8;
        if (k0 + 63 > row0) {
#pragma unroll
            for (int nt = 0; nt < 8; ++nt) {
                int c0 = k0 + nt * 8 + 2 * tig;
                if (c0 > row0) Sacc[nt][0] = -1e30f;
                if (c0 + 1 > row0) Sacc[nt][1] = -1e30f;
                if (c0 > row1) Sacc[nt][2] = -1e30f;
                if (c0 + 1 > row1) Sacc[nt][3] = -1e30f;
            }
        }

        // ---- online softmax (P stays in registers, overwrites Sacc) ----
        float mx0 = -1e30f, mx1 = -1e30f;
#pragma unroll
        for (int nt = 0; nt < 8; ++nt) {
            mx0 = fmaxf(mx0, fmaxf(Sacc[nt][0], Sacc[nt][1]));
            mx1 = fmaxf(mx1, fmaxf(Sacc[nt][2], Sacc[nt][3]));
        }
        mx0 = fmaxf(mx0, __shfl_xor_sync(0xffffffffu, mx0, 1));
        mx0 = fmaxf(mx0, __shfl_xor_sync(0xffffffffu, mx0, 2));
        mx1 = fmaxf(mx1, __shfl_xor_sync(0xffffffffu, mx1, 1));
        mx1 = fmaxf(mx1, __shfl_xor_sync(0xffffffffu, mx1, 2));

        float mn0 = fmaxf(m_i[0], mx0);
        float mn1 = fmaxf(m_i[1], mx1);
        float a0 = __expf(m_i[0] - mn0);
        float a1 = __expf(m_i[1] - mn1);

        float ps0 = 0.f, ps1 = 0.f;
#pragma unroll
        for (int nt = 0; nt < 8; ++nt) {
            Sacc[nt][0] = __expf(Sacc[nt][0] - mn0);
            Sacc[nt][1] = __expf(Sacc[nt][1] - mn0);
            Sacc[nt][2] = __expf(Sacc[nt][2] - mn1);
            Sacc[nt][3] = __expf(Sacc[nt][3] - mn1);
            ps0 += Sacc[nt][0] + Sacc[nt][1];
            ps1 += Sacc[nt][2] + Sacc[nt][3];
        }
        ps0 += __shfl_xor_sync(0xffffffffu, ps0, 1);
        ps0 += __shfl_xor_sync(0xffffffffu, ps0, 2);
        ps1 += __shfl_xor_sync(0xffffffffu, ps1, 1);
        ps1 += __shfl_xor_sync(0xffffffffu, ps1, 2);

        l_i[0] = l_i[0] * a0 + ps0;
        l_i[1] = l_i[1] * a1 + ps1;
        m_i[0] = mn0;
        m_i[1] = mn1;
#pragma unroll
        for (int nt = 0; nt < 8; ++nt) {
            Oacc[nt][0] *= a0;
            Oacc[nt][1] *= a0;
            Oacc[nt][2] *= a1;
            Oacc[nt][3] *= a1;
        }

        // ---- O += P V : shfl transpose of S C-frag -> A-frag ----
        const int src0 = (gid << 2) | (tig >> 1);   // holder of col tig
        const int src1 = src0 + 2;                  // holder of col tig+4
        const bool odd = tig & 1;
#pragma unroll
        for (int g = 0; g < 8; ++g) {
            unsigned t0 = f2tf32(Sacc[g][0]);
            unsigned t1 = f2tf32(Sacc[g][1]);
            unsigned t2 = f2tf32(Sacc[g][2]);
            unsigned t3 = f2tf32(Sacc[g][3]);
            unsigned v00 = __shfl_sync(0xffffffffu, t0, src0);
            unsigned v01 = __shfl_sync(0xffffffffu, t1, src0);
            unsigned v10 = __shfl_sync(0xffffffffu, t2, src0);
            unsigned v11 = __shfl_sync(0xffffffffu, t3, src0);
            unsigned w00 = __shfl_sync(0xffffffffu, t0, src1);
            unsigned w01 = __shfl_sync(0xffffffffu, t1, src1);
            unsigned w10 = __shfl_sync(0xffffffffu, t2, src1);
            unsigned w11 = __shfl_sync(0xffffffffu, t3, src1);
            unsigned af[4];
            af[0] = odd ? v01 : v00;   // P[gid   ][8g+tig]
            af[1] = odd ? v11 : v10;   // P[gid+8 ][8g+tig]
            af[2] = odd ? w01 : w00;   // P[gid   ][8g+tig+4]
            af[3] = odd ? w11 : w10;   // P[gid+8 ][8g+tig+4]
            const int kk = g * 8;
#pragma unroll
            for (int nt = 0; nt < 8; ++nt) {
                unsigned bf[2];
                bf[0] = Vb[(kk + tig) * VP + nt * 8 + gid];
                bf[1] = Vb[(kk + tig + 4) * VP + nt * 8 + gid];
                mma_tf32(Oacc[nt], af, bf);
            }
        }
        buf ^= 1;
    }

    // ---- normalize + write token-major ----
    float inv0 = 1.0f / l_i[0];
    float inv1 = 1.0f / l_i[1];
    const int row0 = q0 + mrow;
    const int row1 = row0 + 8;
#pragma unroll
    for (int nt = 0; nt < 8; ++nt) {
        int col = h * DK_ + nt * 8 + 2 * tig;
        *reinterpret_cast<float2*>(&g_attn[((size_t)(b * S_ + row0)) * D_ + col]) =
            make_float2(Oacc[nt][0] * inv0, Oacc[nt][1] * inv0);
        *reinterpret_cast<float2*>(&g_attn[((size_t)(b * S_ + row1)) * D_ + col]) =
            make_float2(Oacc[nt][2] * inv1, Oacc[nt][3] * inv1);
    }
}

// ---------------------------------------------------------------------------
extern "C" void kernel_launch(void* const* d_in, const int* in_sizes, int n_in,
                              void* d_out, int out_size) {
    const float* x = (const float*)d_in[0];
    const int* pos = (const int*)d_in[1];
    const float* wq = (const float*)d_in[2];
    const float* wk = (const float*)d_in[3];
    const float* wv = (const float*)d_in[4];
    const float* wo = (const float*)d_in[5];
    float* out = (float*)d_out;

    float *qp, *kp, *vp, *attnp;
    cudaGetSymbolAddress((void**)&qp, g_q);
    cudaGetSymbolAddress((void**)&kp, g_k);
    cudaGetSymbolAddress((void**)&vp, g_v);
    cudaGetSymbolAddress((void**)&attnp, g_attn);

    static bool attr_done = false;
    if (!attr_done) {
        cudaFuncSetAttribute(gemm_qkv_kernel,
                             cudaFuncAttributeMaxDynamicSharedMemorySize, GEMM_SMEM);
        cudaFuncSetAttribute(gemm_out_kernel,
                             cudaFuncAttributeMaxDynamicSharedMemorySize, GEMM_SMEM);
        cudaFuncSetAttribute(flash_tf32_kernel,
                             cudaFuncAttributeMaxDynamicSharedMemorySize, FLASH_SMEM);
        attr_done = true;
    }

    dim3 qkv_grid(D_ / 128, M_ / 128, 3);   // (8, 32, 3)
    gemm_qkv_kernel<<<qkv_grid, 256, GEMM_SMEM>>>(x, wq, wk, wv, qp, kp, vp, pos);

    dim3 flash_grid(S_ / 128, B_ * H_);     // (16, 32)
    flash_tf32_kernel<<<flash_grid, 256, FLASH_SMEM>>>();

    dim3 gemm_grid(D_ / 128, M_ / 128);     // (8, 32)
    gemm_out_kernel<<<gemm_grid, 256, GEMM_SMEM>>>(attnp, wo, out);
}

// round 5
// speedup vs baseline: 1.0431x; 1.0431x over previous
#include <cuda_runtime.h>
#include <math.h>

// Problem constants (fixed by the reference).
#define B_ 2
#define S_ 2048
#define D_ 1024
#define H_ 16
#define DK_ 64
#define M_ (B_ * S_)   // 4096 token rows

// Scratch (allocation-free rule: __device__ globals).
__device__ float g_q[B_ * H_ * S_ * DK_];     // [b,h,s,d]
__device__ float g_k[B_ * H_ * S_ * DK_];
__device__ float g_v[B_ * H_ * S_ * DK_];
__device__ float g_attn[M_ * D_];             // [b,s,h*dk]

// ---------------------------------------------------------------------------
// tf32 / cp.async helpers
// ---------------------------------------------------------------------------
__device__ __forceinline__ unsigned f2tf32(float f) {
    unsigned u;
    asm("cvt.rna.tf32.f32 %0, %1;" : "=r"(u) : "f"(f));
    return u;
}

__device__ __forceinline__ void mma_tf32(float (&c)[4], const unsigned (&a)[4],
                                         const unsigned (&b)[2]) {
    asm volatile(
        "mma.sync.aligned.m16n8k8.row.col.f32.tf32.tf32.f32 "
        "{%0,%1,%2,%3}, {%4,%5,%6,%7}, {%8,%9}, {%0,%1,%2,%3};\n"
        : "+f"(c[0]), "+f"(c[1]), "+f"(c[2]), "+f"(c[3])
        : "r"(a[0]), "r"(a[1]), "r"(a[2]), "r"(a[3]), "r"(b[0]), "r"(b[1]));
}

__device__ __forceinline__ void cp_async16(void* smem, const void* gmem) {
    unsigned saddr = (unsigned)__cvta_generic_to_shared(smem);
    asm volatile("cp.async.cg.shared.global [%0], [%1], 16;\n" ::"r"(saddr),
                 "l"(gmem));
}
__device__ __forceinline__ void cp_commit() {
    asm volatile("cp.async.commit_group;\n");
}
template <int N>
__device__ __forceinline__ void cp_wait() {
    asm volatile("cp.async.wait_group %0;\n" ::"n"(N));
}

// ---------------------------------------------------------------------------
// tf32 GEMM body (NT): C[m,n] = sum_k A[m,k] * W[n,k].
// Tile 128x128, BK=32, 256 threads, 8 warps (2m x 4n), warp tile 64x32.
// cp.async raw tiles (double-buffered) -> relayout pass converts to tf32 and
// stores FRAGMENT-MAJOR (single-buffered):
//   AF[g][rb][lane] : uint4  (g = k-group 0..3, rb = 16-row block 0..7)
//   BF[g][nb][lane] : uint2  (nb = 8-col block 0..15)
// mma loop is then pure wide LDS + HMMA (no cvt, no scalar LDS).
// MODE 0: plain write, MODE 1: [b,h,s,d] scatter, MODE 2: scatter + RoPE
// ---------------------------------------------------------------------------
#define GSTRIDE 36
#define GEMM_SMEM ((4 * 128 * GSTRIDE + 2 * 4096) * 4)   // 106496 B

template <int MODE>
__device__ __forceinline__ void gemm_body(
    float* sm, const float* __restrict__ A, const float* __restrict__ W,
    float* __restrict__ Cout, const int* __restrict__ pos) {
    float(*As)[128][GSTRIDE] = reinterpret_cast<float(*)[128][GSTRIDE]>(sm);
    float(*Bs)[128][GSTRIDE] =
        reinterpret_cast<float(*)[128][GSTRIDE]>(sm + 2 * 128 * GSTRIDE);
    unsigned* AF = reinterpret_cast<unsigned*>(sm + 4 * 128 * GSTRIDE);
    unsigned* BF = AF + 4096;

    const int tid = threadIdx.x;
    const int lane = tid & 31;
    const int warp = tid >> 5;
    const int wr = warp >> 2;
    const int wc = warp & 3;
    const int m0 = blockIdx.y * 128;
    const int n0 = blockIdx.x * 128;
    const int gid = lane >> 2;
    const int tig = lane & 3;

    const float* Ab = A + (size_t)m0 * D_;
    const float* Wb = W + (size_t)n0 * D_;

    float acc[4][4][4];
#pragma unroll
    for (int i = 0; i < 4; ++i)
#pragma unroll
        for (int j = 0; j < 4; ++j)
#pragma unroll
            for (int r = 0; r < 4; ++r) acc[i][j][r] = 0.0f;

    auto issue = [&](int buf, int k0) {
#pragma unroll
        for (int i = 0; i < 4; ++i) {
            int l = tid + i * 256;
            int r = l >> 3;
            int c = (l & 7) << 2;
            cp_async16(&As[buf][r][c], Ab + (size_t)r * D_ + k0 + c);
            cp_async16(&Bs[buf][r][c], Wb + (size_t)r * D_ + k0 + c);
        }
        cp_commit();
    };

    const int NIT = D_ / 32;
    issue(0, 0);
    int buf = 0;
    for (int it = 0; it < NIT; ++it) {
        if (it + 1 < NIT) {
            issue(buf ^ 1, (it + 1) * 32);
            cp_wait<1>();
        } else {
            cp_wait<0>();
        }
        __syncthreads();   // raw[buf] landed; prior frag-buffer reads complete

        // ---- relayout: raw fp32 -> tf32 fragment-major (convert ONCE) ----
#pragma unroll
        for (int i = 0; i < 4; ++i) {
            int bi = warp + 8 * i;          // 0..31
            int g = bi >> 3;
            int rb = bi & 7;
            uint4 q;
            q.x = f2tf32(As[buf][rb * 16 + gid][g * 8 + tig]);
            q.y = f2tf32(As[buf][rb * 16 + 8 + gid][g * 8 + tig]);
            q.z = f2tf32(As[buf][rb * 16 + gid][g * 8 + tig + 4]);
            q.w = f2tf32(As[buf][rb * 16 + 8 + gid][g * 8 + tig + 4]);
            *reinterpret_cast<uint4*>(&AF[((g * 8 + rb) * 32 + lane) * 4]) = q;
        }
#pragma unroll
        for (int i = 0; i < 8; ++i) {
            int bi = warp + 8 * i;          // 0..63
            int g = bi >> 4;
            int nb = bi & 15;
            uint2 p;
            p.x = f2tf32(Bs[buf][nb * 8 + gid][g * 8 + tig]);
            p.y = f2tf32(Bs[buf][nb * 8 + gid][g * 8 + tig + 4]);
            *reinterpret_cast<uint2*>(&BF[((g * 16 + nb) * 32 + lane) * 2]) = p;
        }
        __syncthreads();   // frag buffer ready

        // ---- mma: pure wide LDS + HMMA ----
#pragma unroll
        for (int g = 0; g < 4; ++g) {
            unsigned af[4][4], bf[4][2];
#pragma unroll
            for (int mt = 0; mt < 4; ++mt) {
                int rb = wr * 4 + mt;
                uint4 q = *reinterpret_cast<const uint4*>(
                    &AF[((g * 8 + rb) * 32 + lane) * 4]);
                af[mt][0] = q.x; af[mt][1] = q.y;
                af[mt][2] = q.z; af[mt][3] = q.w;
            }
#pragma unroll
            for (int nt = 0; nt < 4; ++nt) {
                int nb = wc * 4 + nt;
                uint2 p = *reinterpret_cast<const uint2*>(
                    &BF[((g * 16 + nb) * 32 + lane) * 2]);
                bf[nt][0] = p.x; bf[nt][1] = p.y;
            }
#pragma unroll
            for (int mt = 0; mt < 4; ++mt)
#pragma unroll
                for (int nt = 0; nt < 4; ++nt) mma_tf32(acc[mt][nt], af[mt], bf[nt]);
        }
        buf ^= 1;
    }

    // ---------------- Epilogue ----------------
#pragma unroll
    for (int mt = 0; mt < 4; ++mt) {
        int row0 = m0 + wr * 64 + mt * 16 + gid;
        int b0i = row0 >> 11, s0i = row0 & (S_ - 1);
        int row1 = row0 + 8;
        int b1i = row1 >> 11, s1i = row1 & (S_ - 1);

        float p0 = 0.f, p1 = 0.f;
        if (MODE == 2) {
            p0 = (float)pos[b0i * S_ + s0i];
            p1 = (float)pos[b1i * S_ + s1i];
        }

#pragma unroll
        for (int nt = 0; nt < 4; ++nt) {
            int col = n0 + wc * 32 + nt * 8 + 2 * tig;
            float e0 = acc[mt][nt][0], o0 = acc[mt][nt][1];
            float e1 = acc[mt][nt][2], o1 = acc[mt][nt][3];

            if (MODE == 2) {
                int j = (col & 63) >> 1;
                float freq = powf(10000.0f, -((float)(2 * j) / 64.0f));
                {
                    float ang = p0 * freq;
                    float cv = (float)cos((double)ang);
                    float sv = (float)sin((double)ang);
                    float re = e0 * cv - o0 * sv;
                    float ro = e0 * sv + o0 * cv;
                    e0 = re; o0 = ro;
                }
                {
                    float ang = p1 * freq;
                    float cv = (float)cos((double)ang);
                    float sv = (float)sin((double)ang);
                    float re = e1 * cv - o1 * sv;
                    float ro = e1 * sv + o1 * cv;
                    e1 = re; o1 = ro;
                }
            }

            if (MODE == 0) {
                *reinterpret_cast<float2*>(Cout + (size_t)row0 * D_ + col) =
                    make_float2(e0, o0);
                *reinterpret_cast<float2*>(Cout + (size_t)row1 * D_ + col) =
                    make_float2(e1, o1);
            } else {
                int h = col >> 6;
                int d = col & 63;
                *reinterpret_cast<float2*>(
                    Cout + (((size_t)(b0i * H_ + h) * S_ + s0i) * DK_ + d)) =
                    make_float2(e0, o0);
                *reinterpret_cast<float2*>(
                    Cout + (((size_t)(b1i * H_ + h) * S_ + s1i) * DK_ + d)) =
                    make_float2(e1, o1);
            }
        }
    }
}

// Merged Q/K/V projection: blockIdx.z selects weight + destination + mode.
__global__ void __launch_bounds__(256, 2) gemm_qkv_kernel(
    const float* __restrict__ x, const float* __restrict__ wq,
    const float* __restrict__ wk, const float* __restrict__ wv,
    float* __restrict__ qp, float* __restrict__ kp, float* __restrict__ vp,
    const int* __restrict__ pos) {
    extern __shared__ float sm[];
    const int z = blockIdx.z;
    if (z == 0)      gemm_body<2>(sm, x, wq, qp, pos);
    else if (z == 1) gemm_body<2>(sm, x, wk, kp, pos);
    else             gemm_body<1>(sm, x, wv, vp, pos);
}

// Output projection.
__global__ void __launch_bounds__(256, 2) gemm_out_kernel(
    const float* __restrict__ A, const float* __restrict__ W,
    float* __restrict__ Cout) {
    extern __shared__ float sm[];
    gemm_body<0>(sm, A, W, Cout, nullptr);
}

// ---------------------------------------------------------------------------
// Flash attention, tf32 tensor cores, causal.  (R2 version — known 248 µs —
// with one strictly-free change: Q pre-converted to tf32 bits at tile load.)
// BM=128 q-rows/CTA, BN=64 keys/iter, dk=64. 256 threads = 8 warps,
// each warp owns 16 q-rows.
// ---------------------------------------------------------------------------
#define FP 68
#define VP 72
#define FLASH_SMEM ((128 * FP + 2 * 64 * FP + 2 * 64 * VP + 128 * FP) * 4)

__global__ void __launch_bounds__(256) flash_tf32_kernel() {
    extern __shared__ float smf[];
    float* Qs = smf;                            // [128][FP] (tf32 bits)
    float* Ks = Qs + 128 * FP;                  // [2][64][FP] raw fp32
    float* Vs = Ks + 2 * 64 * FP;               // [2][64][VP] raw fp32
    float* Ps = Vs + 2 * 64 * VP;               // [128][FP]
    unsigned* Qu = reinterpret_cast<unsigned*>(Qs);

    const int qb = gridDim.x - 1 - blockIdx.x;  // long blocks first
    const int bh = blockIdx.y;
    const int b = bh >> 4;
    const int h = bh & 15;

    const float* Qp = g_q + (size_t)bh * S_ * DK_;
    const float* Kp = g_k + (size_t)bh * S_ * DK_;
    const float* Vp = g_v + (size_t)bh * S_ * DK_;

    const int tid = threadIdx.x;
    const int lane = tid & 31;
    const int warp = tid >> 5;
    const int gid = lane >> 2;
    const int tig = lane & 3;
    const int q0 = qb * 128;
    const int mrow = warp * 16 + gid;

    // Load Q tile: scale by 1/sqrt(dk), convert to tf32 bits once.
#pragma unroll
    for (int i = 0; i < 8; ++i) {
        int l = tid + i * 256;
        int r = l >> 4;
        int c = (l & 15) << 2;
        float4 v = *reinterpret_cast<const float4*>(Qp + (size_t)(q0 + r) * DK_ + c);
        Qu[r * FP + c + 0] = f2tf32(v.x * 0.125f);
        Qu[r * FP + c + 1] = f2tf32(v.y * 0.125f);
        Qu[r * FP + c + 2] = f2tf32(v.z * 0.125f);
        Qu[r * FP + c + 3] = f2tf32(v.w * 0.125f);
    }

    auto issueKV = [&](int bf, int k0) {
#pragma unroll
        for (int i = 0; i < 4; ++i) {
            int l = tid + i * 256;
            int r = l >> 4;
            int c = (l & 15) << 2;
            cp_async16(Ks + bf * 64 * FP + r * FP + c,
                       Kp + (size_t)(k0 + r) * DK_ + c);
            cp_async16(Vs + bf * 64 * VP + r * VP + c,
                       Vp + (size_t)(k0 + r) * DK_ + c);
        }
        cp_commit();
    };

    issueKV(0, 0);

    float m_i[2] = {-1e30f, -1e30f};
    float l_i[2] = {0.f, 0.f};
    float Oacc[8][4];
#pragma unroll
    for (int nt = 0; nt < 8; ++nt)
#pragma unroll
        for (int r = 0; r < 4; ++r) Oacc[nt][r] = 0.0f;

    const int ntiles = 2 * qb + 2;
    int buf = 0;
    for (int kb = 0; kb < ntiles; ++kb) {
        const int k0 = kb * 64;
        cp_wait<0>();
        __syncthreads();                        // tile ready; all warps past reads
        if (kb + 1 < ntiles) issueKV(buf ^ 1, k0 + 64);

        // ---- S = Q K^T ----
        const float* Kb = Ks + buf * 64 * FP;
        float Sacc[8][4];
#pragma unroll
        for (int nt = 0; nt < 8; ++nt)
#pragma unroll
            for (int r = 0; r < 4; ++r) Sacc[nt][r] = 0.0f;

#pragma unroll
        for (int kk = 0; kk < 64; kk += 8) {
            unsigned af[4];
            af[0] = Qu[(mrow) * FP + kk + tig];
            af[1] = Qu[(mrow + 8) * FP + kk + tig];
            af[2] = Qu[(mrow) * FP + kk + tig + 4];
            af[3] = Qu[(mrow + 8) * FP + kk + tig + 4];
#pragma unroll
            for (int nt = 0; nt < 8; ++nt) {
                unsigned bf[2];
                bf[0] = f2tf32(Kb[(nt * 8 + gid) * FP + kk + tig]);
                bf[1] = f2tf32(Kb[(nt * 8 + gid) * FP + kk + tig + 4]);
                mma_tf32(Sacc[nt], af, bf);
            }
        }

        // ---- causal mask ----
        const int row0 = q0 + mrow;
        const int row1 = row0 + 8;
        if (k0 + 63 > row0) {
#pragma unroll
            for (int nt = 0; nt < 8; ++nt) {
                int c0 = k0 + nt * 8 + 2 * tig;
                if (c0 > row0) Sacc[nt][0] = -1e30f;
                if (c0 + 1 > row0) Sacc[nt][1] = -1e30f;
                if (c0 > row1) Sacc[nt][2] = -1e30f;
                if (c0 + 1 > row1) Sacc[nt][3] = -1e30f;
            }
        }

        // ---- online softmax ----
        float mx0 = -1e30f, mx1 = -1e30f;
#pragma unroll
        for (int nt = 0; nt < 8; ++nt) {
            mx0 = fmaxf(mx0, fmaxf(Sacc[nt][0], Sacc[nt][1]));
            mx1 = fmaxf(mx1, fmaxf(Sacc[nt][2], Sacc[nt][3]));
        }
        mx0 = fmaxf(mx0, __shfl_xor_sync(0xffffffffu, mx0, 1));
        mx0 = fmaxf(mx0, __shfl_xor_sync(0xffffffffu, mx0, 2));
        mx1 = fmaxf(mx1, __shfl_xor_sync(0xffffffffu, mx1, 1));
        mx1 = fmaxf(mx1, __shfl_xor_sync(0xffffffffu, mx1, 2));

        float mn0 = fmaxf(m_i[0], mx0);
        float mn1 = fmaxf(m_i[1], mx1);
        float a0 = __expf(m_i[0] - mn0);
        float a1 = __expf(m_i[1] - mn1);

        float ps0 = 0.f, ps1 = 0.f;
#pragma unroll
        for (int nt = 0; nt < 8; ++nt) {
            float p00 = __expf(Sacc[nt][0] - mn0);
            float p01 = __expf(Sacc[nt][1] - mn0);
            float p10 = __expf(Sacc[nt][2] - mn1);
            float p11 = __expf(Sacc[nt][3] - mn1);
            ps0 += p00 + p01;
            ps1 += p10 + p11;
            *reinterpret_cast<float2*>(&Ps[(mrow) * FP + nt * 8 + 2 * tig]) =
                make_float2(p00, p01);
            *reinterpret_cast<float2*>(&Ps[(mrow + 8) * FP + nt * 8 + 2 * tig]) =
                make_float2(p10, p11);
        }
        ps0 += __shfl_xor_sync(0xffffffffu, ps0, 1);
        ps0 += __shfl_xor_sync(0xffffffffu, ps0, 2);
        ps1 += __shfl_xor_sync(0xffffffffu, ps1, 1);
        ps1 += __shfl_xor_sync(0xffffffffu, ps1, 2);

        l_i[0] = l_i[0] * a0 + ps0;
        l_i[1] = l_i[1] * a1 + ps1;
        m_i[0] = mn0;
        m_i[1] = mn1;
#pragma unroll
        for (int nt = 0; nt < 8; ++nt) {
            Oacc[nt][0] *= a0;
            Oacc[nt][1] *= a0;
            Oacc[nt][2] *= a1;
            Oacc[nt][3] *= a1;
        }
        __syncwarp();   // P rows are warp-private

        // ---- O += P V ----
        const float* Vb = Vs + buf * 64 * VP;
#pragma unroll
        for (int kk = 0; kk < 64; kk += 8) {
            unsigned af[4];
            af[0] = f2tf32(Ps[(mrow) * FP + kk + tig]);
            af[1] = f2tf32(Ps[(mrow + 8) * FP + kk + tig]);
            af[2] = f2tf32(Ps[(mrow) * FP + kk + tig + 4]);
            af[3] = f2tf32(Ps[(mrow + 8) * FP + kk + tig + 4]);
#pragma unroll
            for (int nt = 0; nt < 8; ++nt) {
                unsigned bf[2];
                bf[0] = f2tf32(Vb[(kk + tig) * VP + nt * 8 + gid]);
                bf[1] = f2tf32(Vb[(kk + tig + 4) * VP + nt * 8 + gid]);
                mma_tf32(Oacc[nt], af, bf);
            }
        }
        buf ^= 1;
    }

    // ---- normalize + write token-major ----
    float inv0 = 1.0f / l_i[0];
    float inv1 = 1.0f / l_i[1];
    const int row0 = q0 + mrow;
    const int row1 = row0 + 8;
#pragma unroll
    for (int nt = 0; nt < 8; ++nt) {
        int col = h * DK_ + nt * 8 + 2 * tig;
        *reinterpret_cast<float2*>(&g_attn[((size_t)(b * S_ + row0)) * D_ + col]) =
            make_float2(Oacc[nt][0] * inv0, Oacc[nt][1] * inv0);
        *reinterpret_cast<float2*>(&g_attn[((size_t)(b * S_ + row1)) * D_ + col]) =
            make_float2(Oacc[nt][2] * inv1, Oacc[nt][3] * inv1);
    }
}

// ---------------------------------------------------------------------------
extern "C" void kernel_launch(void* const* d_in, const int* in_sizes, int n_in,
                              void* d_out, int out_size) {
    const float* x = (const float*)d_in[0];
    const int* pos = (const int*)d_in[1];
    const float* wq = (const float*)d_in[2];
    const float* wk = (const float*)d_in[3];
    const float* wv = (const float*)d_in[4];
    const float* wo = (const float*)d_in[5];
    float* out = (float*)d_out;

    float *qp, *kp, *vp, *attnp;
    cudaGetSymbolAddress((void**)&qp, g_q);
    cudaGetSymbolAddress((void**)&kp, g_k);
    cudaGetSymbolAddress((void**)&vp, g_v);
    cudaGetSymbolAddress((void**)&attnp, g_attn);

    static bool attr_done = false;
    if (!attr_done) {
        cudaFuncSetAttribute(gemm_qkv_kernel,
                             cudaFuncAttributeMaxDynamicSharedMemorySize, GEMM_SMEM);
        cudaFuncSetAttribute(gemm_out_kernel,
                             cudaFuncAttributeMaxDynamicSharedMemorySize, GEMM_SMEM);
        cudaFuncSetAttribute(flash_tf32_kernel,
                             cudaFuncAttributeMaxDynamicSharedMemorySize, FLASH_SMEM);
        attr_done = true;
    }

    dim3 qkv_grid(D_ / 128, M_ / 128, 3);   // (8, 32, 3)
    gemm_qkv_kernel<<<qkv_grid, 256, GEMM_SMEM>>>(x, wq, wk, wv, qp, kp, vp, pos);

    dim3 flash_grid(S_ / 128, B_ * H_);     // (16, 32)
    flash_tf32_kernel<<<flash_grid, 256, FLASH_SMEM>>>();

    dim3 gemm_grid(D_ / 128, M_ / 128);     // (8, 32)
    gemm_out_kernel<<<gemm_grid, 256, GEMM_SMEM>>>(attnp, wo, out);
}

// round 6
// speedup vs baseline: 1.1149x; 1.0688x over previous
#include <cuda_runtime.h>
#include <math.h>

// Problem constants (fixed by the reference).
#define B_ 2
#define S_ 2048
#define D_ 1024
#define H_ 16
#define DK_ 64
#define M_ (B_ * S_)   // 4096 token rows

// Scratch (allocation-free rule: __device__ globals).
__device__ float g_q[B_ * H_ * S_ * DK_];     // [b,h,s,d]
__device__ float g_k[B_ * H_ * S_ * DK_];
__device__ float g_v[B_ * H_ * S_ * DK_];
__device__ float g_attn[M_ * D_];             // [b,s,h*dk]
__device__ float2 g_rope[B_ * S_ * 32];       // (cos,sin) per (b,s,pair)

// ---------------------------------------------------------------------------
// tf32 / cp.async helpers
// ---------------------------------------------------------------------------
__device__ __forceinline__ unsigned f2tf32(float f) {
    unsigned u;
    asm("cvt.rna.tf32.f32 %0, %1;" : "=r"(u) : "f"(f));
    return u;
}

__device__ __forceinline__ void mma_tf32(float (&c)[4], const unsigned (&a)[4],
                                         const unsigned (&b)[2]) {
    asm volatile(
        "mma.sync.aligned.m16n8k8.row.col.f32.tf32.tf32.f32 "
        "{%0,%1,%2,%3}, {%4,%5,%6,%7}, {%8,%9}, {%0,%1,%2,%3};\n"
        : "+f"(c[0]), "+f"(c[1]), "+f"(c[2]), "+f"(c[3])
        : "r"(a[0]), "r"(a[1]), "r"(a[2]), "r"(a[3]), "r"(b[0]), "r"(b[1]));
}

__device__ __forceinline__ void cp_async16(void* smem, const void* gmem) {
    unsigned saddr = (unsigned)__cvta_generic_to_shared(smem);
    asm volatile("cp.async.cg.shared.global [%0], [%1], 16;\n" ::"r"(saddr),
                 "l"(gmem));
}
__device__ __forceinline__ void cp_commit() {
    asm volatile("cp.async.commit_group;\n");
}
template <int N>
__device__ __forceinline__ void cp_wait() {
    asm volatile("cp.async.wait_group %0;\n" ::"n"(N));
}

// ---------------------------------------------------------------------------
// RoPE table: g_rope[(b*S+s)*32 + j] = (cos, sin) of pos[b,s] * theta^(-2j/64).
// Same fp32 angle computation as before; fp32 trig (delta vs double ~1e-7).
// ---------------------------------------------------------------------------
__global__ void rope_table_kernel(const int* __restrict__ pos) {
    int t = blockIdx.x * blockDim.x + threadIdx.x;   // 131072 threads
    int j = t & 31;
    int s = (t >> 5) & (S_ - 1);
    int b = t >> 16;
    float p = (float)pos[b * S_ + s];
    float freq = powf(10000.0f, -((float)(2 * j) / 64.0f));
    float ang = p * freq;
    float sv, cv;
    sincosf(ang, &sv, &cv);
    g_rope[t] = make_float2(cv, sv);
}

// ---------------------------------------------------------------------------
// tf32 GEMM body (NT): C[m,n] = sum_k A[m,k] * W[n,k].  (R1-proven structure)
// Tile 128x128, BK=32, 256 threads, 8 warps (2m x 4n), warp tile 64x32.
// MODE 0: plain write, MODE 1: [b,h,s,d] scatter, MODE 2: scatter + RoPE(table)
// ---------------------------------------------------------------------------
#define GSTRIDE 36
#define GEMM_SMEM (2 * 2 * 128 * GSTRIDE * 4)   // 73728 B

template <int MODE>
__device__ __forceinline__ void gemm_body(
    float* sm, const float* __restrict__ A, const float* __restrict__ W,
    float* __restrict__ Cout) {
    float(*As)[128][GSTRIDE] = reinterpret_cast<float(*)[128][GSTRIDE]>(sm);
    float(*Bs)[128][GSTRIDE] =
        reinterpret_cast<float(*)[128][GSTRIDE]>(sm + 2 * 128 * GSTRIDE);

    const int tid = threadIdx.x;
    const int lane = tid & 31;
    const int warp = tid >> 5;
    const int wr = warp >> 2;
    const int wc = warp & 3;
    const int m0 = blockIdx.y * 128;
    const int n0 = blockIdx.x * 128;
    const int gid = lane >> 2;
    const int tig = lane & 3;

    const float* Ab = A + (size_t)m0 * D_;
    const float* Wb = W + (size_t)n0 * D_;

    float acc[4][4][4];
#pragma unroll
    for (int i = 0; i < 4; ++i)
#pragma unroll
        for (int j = 0; j < 4; ++j)
#pragma unroll
            for (int r = 0; r < 4; ++r) acc[i][j][r] = 0.0f;

    auto issue = [&](int buf, int k0) {
#pragma unroll
        for (int i = 0; i < 4; ++i) {
            int l = tid + i * 256;
            int r = l >> 3;
            int c = (l & 7) << 2;
            cp_async16(&As[buf][r][c], Ab + (size_t)r * D_ + k0 + c);
            cp_async16(&Bs[buf][r][c], Wb + (size_t)r * D_ + k0 + c);
        }
        cp_commit();
    };

    const int NIT = D_ / 32;
    issue(0, 0);
    int buf = 0;
    for (int it = 0; it < NIT; ++it) {
        if (it + 1 < NIT) {
            issue(buf ^ 1, (it + 1) * 32);
            cp_wait<1>();
        } else {
            cp_wait<0>();
        }
        __syncthreads();

#pragma unroll
        for (int kk = 0; kk < 32; kk += 8) {
            unsigned af[4][4], bf[4][2];
#pragma unroll
            for (int mt = 0; mt < 4; ++mt) {
                int r = wr * 64 + mt * 16 + gid;
                af[mt][0] = f2tf32(As[buf][r][kk + tig]);
                af[mt][1] = f2tf32(As[buf][r + 8][kk + tig]);
                af[mt][2] = f2tf32(As[buf][r][kk + tig + 4]);
                af[mt][3] = f2tf32(As[buf][r + 8][kk + tig + 4]);
            }
#pragma unroll
            for (int nt = 0; nt < 4; ++nt) {
                int rn = wc * 32 + nt * 8 + gid;
                bf[nt][0] = f2tf32(Bs[buf][rn][kk + tig]);
                bf[nt][1] = f2tf32(Bs[buf][rn][kk + tig + 4]);
            }
#pragma unroll
            for (int mt = 0; mt < 4; ++mt)
#pragma unroll
                for (int nt = 0; nt < 4; ++nt) mma_tf32(acc[mt][nt], af[mt], bf[nt]);
        }
        __syncthreads();
        buf ^= 1;
    }

    // ---------------- Epilogue ----------------
#pragma unroll
    for (int mt = 0; mt < 4; ++mt) {
        int row0 = m0 + wr * 64 + mt * 16 + gid;
        int b0i = row0 >> 11, s0i = row0 & (S_ - 1);
        int row1 = row0 + 8;
        int b1i = row1 >> 11, s1i = row1 & (S_ - 1);

#pragma unroll
        for (int nt = 0; nt < 4; ++nt) {
            int col = n0 + wc * 32 + nt * 8 + 2 * tig;
            float e0 = acc[mt][nt][0], o0 = acc[mt][nt][1];
            float e1 = acc[mt][nt][2], o1 = acc[mt][nt][3];

            if (MODE == 2) {
                int j = (col & 63) >> 1;
                float2 cs0 = g_rope[(size_t)(b0i * S_ + s0i) * 32 + j];
                float2 cs1 = g_rope[(size_t)(b1i * S_ + s1i) * 32 + j];
                float re0 = e0 * cs0.x - o0 * cs0.y;
                float ro0 = e0 * cs0.y + o0 * cs0.x;
                float re1 = e1 * cs1.x - o1 * cs1.y;
                float ro1 = e1 * cs1.y + o1 * cs1.x;
                e0 = re0; o0 = ro0; e1 = re1; o1 = ro1;
            }

            if (MODE == 0) {
                *reinterpret_cast<float2*>(Cout + (size_t)row0 * D_ + col) =
                    make_float2(e0, o0);
                *reinterpret_cast<float2*>(Cout + (size_t)row1 * D_ + col) =
                    make_float2(e1, o1);
            } else {
                int h = col >> 6;
                int d = col & 63;
                *reinterpret_cast<float2*>(
                    Cout + (((size_t)(b0i * H_ + h) * S_ + s0i) * DK_ + d)) =
                    make_float2(e0, o0);
                *reinterpret_cast<float2*>(
                    Cout + (((size_t)(b1i * H_ + h) * S_ + s1i) * DK_ + d)) =
                    make_float2(e1, o1);
            }
        }
    }
}

// Merged Q/K/V projection: blockIdx.z selects weight + destination + mode.
__global__ void __launch_bounds__(256) gemm_qkv_kernel(
    const float* __restrict__ x, const float* __restrict__ wq,
    const float* __restrict__ wk, const float* __restrict__ wv,
    float* __restrict__ qp, float* __restrict__ kp, float* __restrict__ vp) {
    extern __shared__ float sm[];
    const int z = blockIdx.z;
    if (z == 0)      gemm_body<2>(sm, x, wq, qp);
    else if (z == 1) gemm_body<2>(sm, x, wk, kp);
    else             gemm_body<1>(sm, x, wv, vp);
}

// Output projection.
__global__ void __launch_bounds__(256) gemm_out_kernel(
    const float* __restrict__ A, const float* __restrict__ W,
    float* __restrict__ Cout) {
    extern __shared__ float sm[];
    gemm_body<0>(sm, A, W, Cout);
}

// ---------------------------------------------------------------------------
// Flash attention, tf32 tensor cores, causal. (Proven R2 structure +
// Q pre-converted to tf32 bits at tile load.)
// BM=128 q-rows/CTA, BN=64 keys/iter, dk=64. 256 threads = 8 warps.
// ---------------------------------------------------------------------------
#define FP 68
#define VP 72
#define FLASH_SMEM ((128 * FP + 2 * 64 * FP + 2 * 64 * VP + 128 * FP) * 4)

__global__ void __launch_bounds__(256) flash_tf32_kernel() {
    extern __shared__ float smf[];
    float* Qs = smf;                            // [128][FP] (tf32 bits)
    float* Ks = Qs + 128 * FP;                  // [2][64][FP] raw fp32
    float* Vs = Ks + 2 * 64 * FP;               // [2][64][VP] raw fp32
    float* Ps = Vs + 2 * 64 * VP;               // [128][FP]
    unsigned* Qu = reinterpret_cast<unsigned*>(Qs);

    const int qb = gridDim.x - 1 - blockIdx.x;  // long blocks first
    const int bh = blockIdx.y;
    const int b = bh >> 4;
    const int h = bh & 15;

    const float* Qp = g_q + (size_t)bh * S_ * DK_;
    const float* Kp = g_k + (size_t)bh * S_ * DK_;
    const float* Vp = g_v + (size_t)bh * S_ * DK_;

    const int tid = threadIdx.x;
    const int lane = tid & 31;
    const int warp = tid >> 5;
    const int gid = lane >> 2;
    const int tig = lane & 3;
    const int q0 = qb * 128;
    const int mrow = warp * 16 + gid;

    // Load Q tile: scale by 1/sqrt(dk), convert to tf32 bits once.
#pragma unroll
    for (int i = 0; i < 8; ++i) {
        int l = tid + i * 256;
        int r = l >> 4;
        int c = (l & 15) << 2;
        float4 v = *reinterpret_cast<const float4*>(Qp + (size_t)(q0 + r) * DK_ + c);
        Qu[r * FP + c + 0] = f2tf32(v.x * 0.125f);
        Qu[r * FP + c + 1] = f2tf32(v.y * 0.125f);
        Qu[r * FP + c + 2] = f2tf32(v.z * 0.125f);
        Qu[r * FP + c + 3] = f2tf32(v.w * 0.125f);
    }

    auto issueKV = [&](int bf, int k0) {
#pragma unroll
        for (int i = 0; i < 4; ++i) {
            int l = tid + i * 256;
            int r = l >> 4;
            int c = (l & 15) << 2;
            cp_async16(Ks + bf * 64 * FP + r * FP + c,
                       Kp + (size_t)(k0 + r) * DK_ + c);
            cp_async16(Vs + bf * 64 * VP + r * VP + c,
                       Vp + (size_t)(k0 + r) * DK_ + c);
        }
        cp_commit();
    };

    issueKV(0, 0);

    float m_i[2] = {-1e30f, -1e30f};
    float l_i[2] = {0.f, 0.f};
    float Oacc[8][4];
#pragma unroll
    for (int nt = 0; nt < 8; ++nt)
#pragma unroll
        for (int r = 0; r < 4; ++r) Oacc[nt][r] = 0.0f;

    const int ntiles = 2 * qb + 2;
    int buf = 0;
    for (int kb = 0; kb < ntiles; ++kb) {
        const int k0 = kb * 64;
        cp_wait<0>();
        __syncthreads();                        // tile ready; all warps past reads
        if (kb + 1 < ntiles) issueKV(buf ^ 1, k0 + 64);

        // ---- S = Q K^T ----
        const float* Kb = Ks + buf * 64 * FP;
        float Sacc[8][4];
#pragma unroll
        for (int nt = 0; nt < 8; ++nt)
#pragma unroll
            for (int r = 0; r < 4; ++r) Sacc[nt][r] = 0.0f;

#pragma unroll
        for (int kk = 0; kk < 64; kk += 8) {
            unsigned af[4];
            af[0] = Qu[(mrow) * FP + kk + tig];
            af[1] = Qu[(mrow + 8) * FP + kk + tig];
            af[2] = Qu[(mrow) * FP + kk + tig + 4];
            af[3] = Qu[(mrow + 8) * FP + kk + tig + 4];
#pragma unroll
            for (int nt = 0; nt < 8; ++nt) {
                unsigned bf[2];
                bf[0] = f2tf32(Kb[(nt * 8 + gid) * FP + kk + tig]);
                bf[1] = f2tf32(Kb[(nt * 8 + gid) * FP + kk + tig + 4]);
                mma_tf32(Sacc[nt], af, bf);
            }
        }

        // ---- causal mask ----
        const int row0 = q0 + mrow;
        const int row1 = row0 + 8;
        if (k0 + 63 > row0) {
#pragma unroll
            for (int nt = 0; nt < 8; ++nt) {
                int c0 = k0 + nt * 8 + 2 * tig;
                if (c0 > row0) Sacc[nt][0] = -1e30f;
                if (c0 + 1 > row0) Sacc[nt][1] = -1e30f;
                if (c0 > row1) Sacc[nt][2] = -1e30f;
                if (c0 + 1 > row1) Sacc[nt][3] = -1e30f;
            }
        }

        // ---- online softmax ----
        float mx0 = -1e30f, mx1 = -1e30f;
#pragma unroll
        for (int nt = 0; nt < 8; ++nt) {
            mx0 = fmaxf(mx0, fmaxf(Sacc[nt][0], Sacc[nt][1]));
            mx1 = fmaxf(mx1, fmaxf(Sacc[nt][2], Sacc[nt][3]));
        }
        mx0 = fmaxf(mx0, __shfl_xor_sync(0xffffffffu, mx0, 1));
        mx0 = fmaxf(mx0, __shfl_xor_sync(0xffffffffu, mx0, 2));
        mx1 = fmaxf(mx1, __shfl_xor_sync(0xffffffffu, mx1, 1));
        mx1 = fmaxf(mx1, __shfl_xor_sync(0xffffffffu, mx1, 2));

        float mn0 = fmaxf(m_i[0], mx0);
        float mn1 = fmaxf(m_i[1], mx1);
        float a0 = __expf(m_i[0] - mn0);
        float a1 = __expf(m_i[1] - mn1);

        float ps0 = 0.f, ps1 = 0.f;
#pragma unroll
        for (int nt = 0; nt < 8; ++nt) {
            float p00 = __expf(Sacc[nt][0] - mn0);
            float p01 = __expf(Sacc[nt][1] - mn0);
            float p10 = __expf(Sacc[nt][2] - mn1);
            float p11 = __expf(Sacc[nt][3] - mn1);
            ps0 += p00 + p01;
            ps1 += p10 + p11;
            *reinterpret_cast<float2*>(&Ps[(mrow) * FP + nt * 8 + 2 * tig]) =
                make_float2(p00, p01);
            *reinterpret_cast<float2*>(&Ps[(mrow + 8) * FP + nt * 8 + 2 * tig]) =
                make_float2(p10, p11);
        }
        ps0 += __shfl_xor_sync(0xffffffffu, ps0, 1);
        ps0 += __shfl_xor_sync(0xffffffffu, ps0, 2);
        ps1 += __shfl_xor_sync(0xffffffffu, ps1, 1);
        ps1 += __shfl_xor_sync(0xffffffffu, ps1, 2);

        l_i[0] = l_i[0] * a0 + ps0;
        l_i[1] = l_i[1] * a1 + ps1;
        m_i[0] = mn0;
        m_i[1] = mn1;
#pragma unroll
        for (int nt = 0; nt < 8; ++nt) {
            Oacc[nt][0] *= a0;
            Oacc[nt][1] *= a0;
            Oacc[nt][2] *= a1;
            Oacc[nt][3] *= a1;
        }
        __syncwarp();   // P rows are warp-private

        // ---- O += P V ----
        const float* Vb = Vs + buf * 64 * VP;
#pragma unroll
        for (int kk = 0; kk < 64; kk += 8) {
            unsigned af[4];
            af[0] = f2tf32(Ps[(mrow) * FP + kk + tig]);
            af[1] = f2tf32(Ps[(mrow + 8) * FP + kk + tig]);
            af[2] = f2tf32(Ps[(mrow) * FP + kk + tig + 4]);
            af[3] = f2tf32(Ps[(mrow + 8) * FP + kk + tig + 4]);
#pragma unroll
            for (int nt = 0; nt < 8; ++nt) {
                unsigned bf[2];
                bf[0] = f2tf32(Vb[(kk + tig) * VP + nt * 8 + gid]);
                bf[1] = f2tf32(Vb[(kk + tig + 4) * VP + nt * 8 + gid]);
                mma_tf32(Oacc[nt], af, bf);
            }
        }
        buf ^= 1;
    }

    // ---- normalize + write token-major ----
    float inv0 = 1.0f / l_i[0];
    float inv1 = 1.0f / l_i[1];
    const int row0 = q0 + mrow;
    const int row1 = row0 + 8;
#pragma unroll
    for (int nt = 0; nt < 8; ++nt) {
        int col = h * DK_ + nt * 8 + 2 * tig;
        *reinterpret_cast<float2*>(&g_attn[((size_t)(b * S_ + row0)) * D_ + col]) =
            make_float2(Oacc[nt][0] * inv0, Oacc[nt][1] * inv0);
        *reinterpret_cast<float2*>(&g_attn[((size_t)(b * S_ + row1)) * D_ + col]) =
            make_float2(Oacc[nt][2] * inv1, Oacc[nt][3] * inv1);
    }
}

// ---------------------------------------------------------------------------
extern "C" void kernel_launch(void* const* d_in, const int* in_sizes, int n_in,
                              void* d_out, int out_size) {
    const float* x = (const float*)d_in[0];
    const int* pos = (const int*)d_in[1];
    const float* wq = (const float*)d_in[2];
    const float* wk = (const float*)d_in[3];
    const float* wv = (const float*)d_in[4];
    const float* wo = (const float*)d_in[5];
    float* out = (float*)d_out;

    float *qp, *kp, *vp, *attnp;
    cudaGetSymbolAddress((void**)&qp, g_q);
    cudaGetSymbolAddress((void**)&kp, g_k);
    cudaGetSymbolAddress((void**)&vp, g_v);
    cudaGetSymbolAddress((void**)&attnp, g_attn);

    static bool attr_done = false;
    if (!attr_done) {
        cudaFuncSetAttribute(gemm_qkv_kernel,
                             cudaFuncAttributeMaxDynamicSharedMemorySize, GEMM_SMEM);
        cudaFuncSetAttribute(gemm_out_kernel,
                             cudaFuncAttributeMaxDynamicSharedMemorySize, GEMM_SMEM);
        cudaFuncSetAttribute(flash_tf32_kernel,
                             cudaFuncAttributeMaxDynamicSharedMemorySize, FLASH_SMEM);
        attr_done = true;
    }

    // RoPE cos/sin table (fp32 trig; angle computed in fp32 as before).
    rope_table_kernel<<<(B_ * S_ * 32) / 256, 256>>>(pos);

    dim3 qkv_grid(D_ / 128, M_ / 128, 3);   // (8, 32, 3)
    gemm_qkv_kernel<<<qkv_grid, 256, GEMM_SMEM>>>(x, wq, wk, wv, qp, kp, vp);

    dim3 flash_grid(S_ / 128, B_ * H_);     // (16, 32)
    flash_tf32_kernel<<<flash_grid, 256, FLASH_SMEM>>>();

    dim3 gemm_grid(D_ / 128, M_ / 128);     // (8, 32)
    gemm_out_kernel<<<gemm_grid, 256, GEMM_SMEM>>>(attnp, wo, out);
}

// round 7
// speedup vs baseline: 1.1443x; 1.0264x over previous
#include <cuda_runtime.h>
#include <math.h>

// Problem constants (fixed by the reference).
#define B_ 2
#define S_ 2048
#define D_ 1024
#define H_ 16
#define DK_ 64
#define M_ (B_ * S_)   // 4096 token rows

// Scratch (allocation-free rule: __device__ globals).
__device__ float g_q[B_ * H_ * S_ * DK_];     // [b,h,s,d]
__device__ float g_k[B_ * H_ * S_ * DK_];
__device__ float g_v[B_ * H_ * S_ * DK_];
__device__ float g_attn[M_ * D_];             // [b,s,h*dk]
__device__ float2 g_rope[B_ * S_ * 32];       // (cos,sin) per (b,s,pair)

// ---------------------------------------------------------------------------
// tf32 / cp.async helpers
// ---------------------------------------------------------------------------
__device__ __forceinline__ unsigned f2tf32(float f) {
    unsigned u;
    asm("cvt.rna.tf32.f32 %0, %1;" : "=r"(u) : "f"(f));
    return u;
}

__device__ __forceinline__ void mma_tf32(float (&c)[4], const unsigned (&a)[4],
                                         const unsigned (&b)[2]) {
    asm volatile(
        "mma.sync.aligned.m16n8k8.row.col.f32.tf32.tf32.f32 "
        "{%0,%1,%2,%3}, {%4,%5,%6,%7}, {%8,%9}, {%0,%1,%2,%3};\n"
        : "+f"(c[0]), "+f"(c[1]), "+f"(c[2]), "+f"(c[3])
        : "r"(a[0]), "r"(a[1]), "r"(a[2]), "r"(a[3]), "r"(b[0]), "r"(b[1]));
}

__device__ __forceinline__ void cp_async16(void* smem, const void* gmem) {
    unsigned saddr = (unsigned)__cvta_generic_to_shared(smem);
    asm volatile("cp.async.cg.shared.global [%0], [%1], 16;\n" ::"r"(saddr),
                 "l"(gmem));
}
__device__ __forceinline__ void cp_commit() {
    asm volatile("cp.async.commit_group;\n");
}
template <int N>
__device__ __forceinline__ void cp_wait() {
    asm volatile("cp.async.wait_group %0;\n" ::"n"(N));
}

// ---------------------------------------------------------------------------
// RoPE table: g_rope[(b*S+s)*32 + j] = (cos, sin) of pos[b,s] * theta^(-2j/64).
// ---------------------------------------------------------------------------
__global__ void rope_table_kernel(const int* __restrict__ pos) {
    int t = blockIdx.x * blockDim.x + threadIdx.x;   // 131072 threads
    int j = t & 31;
    int s = (t >> 5) & (S_ - 1);
    int b = t >> 16;
    float p = (float)pos[b * S_ + s];
    float freq = powf(10000.0f, -((float)(2 * j) / 64.0f));
    float ang = p * freq;
    float sv, cv;
    sincosf(ang, &sv, &cv);
    g_rope[t] = make_float2(cv, sv);
}

// ---------------------------------------------------------------------------
// tf32 GEMM body (NT): C[m,n] = sum_k A[m,k] * W[n,k].
// Tile 128x128, BK=32, 256 threads, 8 warps (2m x 4n), warp tile 64x32.
// 3-stage cp.async pipeline, ONE __syncthreads per K-iteration.
// MODE 0: plain write, MODE 1: [b,h,s,d] scatter, MODE 2: scatter + RoPE(table)
// ---------------------------------------------------------------------------
#define GSTRIDE 36
#define GEMM_SMEM (3 * 2 * 128 * GSTRIDE * 4)   // 110592 B

template <int MODE>
__device__ __forceinline__ void gemm_body(
    float* sm, const float* __restrict__ A, const float* __restrict__ W,
    float* __restrict__ Cout) {
    // Stage s occupies sm + s * (2*128*GSTRIDE): As then Bs.
    const int tid = threadIdx.x;
    const int lane = tid & 31;
    const int warp = tid >> 5;
    const int wr = warp >> 2;
    const int wc = warp & 3;
    const int m0 = blockIdx.y * 128;
    const int n0 = blockIdx.x * 128;
    const int gid = lane >> 2;
    const int tig = lane & 3;

    const float* Ab = A + (size_t)m0 * D_;
    const float* Wb = W + (size_t)n0 * D_;

    float acc[4][4][4];
#pragma unroll
    for (int i = 0; i < 4; ++i)
#pragma unroll
        for (int j = 0; j < 4; ++j)
#pragma unroll
            for (int r = 0; r < 4; ++r) acc[i][j][r] = 0.0f;

    auto issue = [&](int st, int k0) {
        float(*As)[GSTRIDE] =
            reinterpret_cast<float(*)[GSTRIDE]>(sm + st * 2 * 128 * GSTRIDE);
        float(*Bs)[GSTRIDE] = reinterpret_cast<float(*)[GSTRIDE]>(
            sm + st * 2 * 128 * GSTRIDE + 128 * GSTRIDE);
#pragma unroll
        for (int i = 0; i < 4; ++i) {
            int l = tid + i * 256;
            int r = l >> 3;
            int c = (l & 7) << 2;
            cp_async16(&As[r][c], Ab + (size_t)r * D_ + k0 + c);
            cp_async16(&Bs[r][c], Wb + (size_t)r * D_ + k0 + c);
        }
        cp_commit();
    };

    const int NIT = D_ / 32;
    issue(0, 0);
    issue(1, 32);
    int st = 0;
    for (int it = 0; it < NIT; ++it) {
        if (it + 1 < NIT) {
            cp_wait<1>();
        } else {
            cp_wait<0>();
        }
        __syncthreads();   // stage st ready; all threads done reading stage st-1

        // Prefetch into the slot read at iter it-1 (safe after the barrier).
        if (it + 2 < NIT) issue((st + 2) % 3, (it + 2) * 32);

        float(*As)[GSTRIDE] =
            reinterpret_cast<float(*)[GSTRIDE]>(sm + st * 2 * 128 * GSTRIDE);
        float(*Bs)[GSTRIDE] = reinterpret_cast<float(*)[GSTRIDE]>(
            sm + st * 2 * 128 * GSTRIDE + 128 * GSTRIDE);

#pragma unroll
        for (int kk = 0; kk < 32; kk += 8) {
            unsigned af[4][4], bf[4][2];
#pragma unroll
            for (int mt = 0; mt < 4; ++mt) {
                int r = wr * 64 + mt * 16 + gid;
                af[mt][0] = f2tf32(As[r][kk + tig]);
                af[mt][1] = f2tf32(As[r + 8][kk + tig]);
                af[mt][2] = f2tf32(As[r][kk + tig + 4]);
                af[mt][3] = f2tf32(As[r + 8][kk + tig + 4]);
            }
#pragma unroll
            for (int nt = 0; nt < 4; ++nt) {
                int rn = wc * 32 + nt * 8 + gid;
                bf[nt][0] = f2tf32(Bs[rn][kk + tig]);
                bf[nt][1] = f2tf32(Bs[rn][kk + tig + 4]);
            }
#pragma unroll
            for (int mt = 0; mt < 4; ++mt)
#pragma unroll
                for (int nt = 0; nt < 4; ++nt) mma_tf32(acc[mt][nt], af[mt], bf[nt]);
        }
        st = (st + 1) % 3;
    }

    // ---------------- Epilogue ----------------
#pragma unroll
    for (int mt = 0; mt < 4; ++mt) {
        int row0 = m0 + wr * 64 + mt * 16 + gid;
        int b0i = row0 >> 11, s0i = row0 & (S_ - 1);
        int row1 = row0 + 8;
        int b1i = row1 >> 11, s1i = row1 & (S_ - 1);

#pragma unroll
        for (int nt = 0; nt < 4; ++nt) {
            int col = n0 + wc * 32 + nt * 8 + 2 * tig;
            float e0 = acc[mt][nt][0], o0 = acc[mt][nt][1];
            float e1 = acc[mt][nt][2], o1 = acc[mt][nt][3];

            if (MODE == 2) {
                int j = (col & 63) >> 1;
                float2 cs0 = g_rope[(size_t)(b0i * S_ + s0i) * 32 + j];
                float2 cs1 = g_rope[(size_t)(b1i * S_ + s1i) * 32 + j];
                float re0 = e0 * cs0.x - o0 * cs0.y;
                float ro0 = e0 * cs0.y + o0 * cs0.x;
                float re1 = e1 * cs1.x - o1 * cs1.y;
                float ro1 = e1 * cs1.y + o1 * cs1.x;
                e0 = re0; o0 = ro0; e1 = re1; o1 = ro1;
            }

            if (MODE == 0) {
                *reinterpret_cast<float2*>(Cout + (size_t)row0 * D_ + col) =
                    make_float2(e0, o0);
                *reinterpret_cast<float2*>(Cout + (size_t)row1 * D_ + col) =
                    make_float2(e1, o1);
            } else {
                int h = col >> 6;
                int d = col & 63;
                *reinterpret_cast<float2*>(
                    Cout + (((size_t)(b0i * H_ + h) * S_ + s0i) * DK_ + d)) =
                    make_float2(e0, o0);
                *reinterpret_cast<float2*>(
                    Cout + (((size_t)(b1i * H_ + h) * S_ + s1i) * DK_ + d)) =
                    make_float2(e1, o1);
            }
        }
    }
}

// Merged Q/K/V projection: blockIdx.z selects weight + destination + mode.
__global__ void __launch_bounds__(256, 2) gemm_qkv_kernel(
    const float* __restrict__ x, const float* __restrict__ wq,
    const float* __restrict__ wk, const float* __restrict__ wv,
    float* __restrict__ qp, float* __restrict__ kp, float* __restrict__ vp) {
    extern __shared__ float sm[];
    const int z = blockIdx.z;
    if (z == 0)      gemm_body<2>(sm, x, wq, qp);
    else if (z == 1) gemm_body<2>(sm, x, wk, kp);
    else             gemm_body<1>(sm, x, wv, vp);
}

// Output projection.
__global__ void __launch_bounds__(256, 2) gemm_out_kernel(
    const float* __restrict__ A, const float* __restrict__ W,
    float* __restrict__ Cout) {
    extern __shared__ float sm[];
    gemm_body<0>(sm, A, W, Cout);
}

// ---------------------------------------------------------------------------
// Flash attention, tf32 tensor cores, causal.  Proven R2 inner structure,
// re-tiled: BM=64 q-rows/CTA, 128 threads (4 warps x 16 rows) -> 106.5 KB
// smem -> 2 CTAs/SM for barrier/latency decoupling.
// ---------------------------------------------------------------------------
#define FP 68
#define VP 72
#define FLASH_SMEM ((64 * FP + 2 * 64 * FP + 2 * 64 * VP + 64 * FP) * 4)

__global__ void __launch_bounds__(128, 2) flash_tf32_kernel() {
    extern __shared__ float smf[];
    float* Qs = smf;                            // [64][FP] (tf32 bits)
    float* Ks = Qs + 64 * FP;                   // [2][64][FP] raw fp32
    float* Vs = Ks + 2 * 64 * FP;               // [2][64][VP] raw fp32
    float* Ps = Vs + 2 * 64 * VP;               // [64][FP]
    unsigned* Qu = reinterpret_cast<unsigned*>(Qs);

    const int qb = gridDim.x - 1 - blockIdx.x;  // long blocks first
    const int bh = blockIdx.y;
    const int b = bh >> 4;
    const int h = bh & 15;

    const float* Qp = g_q + (size_t)bh * S_ * DK_;
    const float* Kp = g_k + (size_t)bh * S_ * DK_;
    const float* Vp = g_v + (size_t)bh * S_ * DK_;

    const int tid = threadIdx.x;
    const int lane = tid & 31;
    const int warp = tid >> 5;                  // 0..3
    const int gid = lane >> 2;
    const int tig = lane & 3;
    const int q0 = qb * 64;
    const int mrow = warp * 16 + gid;           // 0..63

    // Load Q tile: scale by 1/sqrt(dk), convert to tf32 bits once.
#pragma unroll
    for (int i = 0; i < 8; ++i) {
        int l = tid + i * 128;
        int r = l >> 4;
        int c = (l & 15) << 2;
        float4 v = *reinterpret_cast<const float4*>(Qp + (size_t)(q0 + r) * DK_ + c);
        Qu[r * FP + c + 0] = f2tf32(v.x * 0.125f);
        Qu[r * FP + c + 1] = f2tf32(v.y * 0.125f);
        Qu[r * FP + c + 2] = f2tf32(v.z * 0.125f);
        Qu[r * FP + c + 3] = f2tf32(v.w * 0.125f);
    }

    auto issueKV = [&](int bf, int k0) {
#pragma unroll
        for (int i = 0; i < 8; ++i) {
            int l = tid + i * 128;
            int r = l >> 4;
            int c = (l & 15) << 2;
            cp_async16(Ks + bf * 64 * FP + r * FP + c,
                       Kp + (size_t)(k0 + r) * DK_ + c);
            cp_async16(Vs + bf * 64 * VP + r * VP + c,
                       Vp + (size_t)(k0 + r) * DK_ + c);
        }
        cp_commit();
    };

    issueKV(0, 0);

    float m_i[2] = {-1e30f, -1e30f};
    float l_i[2] = {0.f, 0.f};
    float Oacc[8][4];
#pragma unroll
    for (int nt = 0; nt < 8; ++nt)
#pragma unroll
        for (int r = 0; r < 4; ++r) Oacc[nt][r] = 0.0f;

    const int ntiles = qb + 1;
    int buf = 0;
    for (int kb = 0; kb < ntiles; ++kb) {
        const int k0 = kb * 64;
        cp_wait<0>();
        __syncthreads();                        // tile ready; all warps past reads
        if (kb + 1 < ntiles) issueKV(buf ^ 1, k0 + 64);

        // ---- S = Q K^T ----
        const float* Kb = Ks + buf * 64 * FP;
        float Sacc[8][4];
#pragma unroll
        for (int nt = 0; nt < 8; ++nt)
#pragma unroll
            for (int r = 0; r < 4; ++r) Sacc[nt][r] = 0.0f;

#pragma unroll
        for (int kk = 0; kk < 64; kk += 8) {
            unsigned af[4];
            af[0] = Qu[(mrow) * FP + kk + tig];
            af[1] = Qu[(mrow + 8) * FP + kk + tig];
            af[2] = Qu[(mrow) * FP + kk + tig + 4];
            af[3] = Qu[(mrow + 8) * FP + kk + tig + 4];
#pragma unroll
            for (int nt = 0; nt < 8; ++nt) {
                unsigned bf[2];
                bf[0] = f2tf32(Kb[(nt * 8 + gid) * FP + kk + tig]);
                bf[1] = f2tf32(Kb[(nt * 8 + gid) * FP + kk + tig + 4]);
                mma_tf32(Sacc[nt], af, bf);
            }
        }

        // ---- causal mask ----
        const int row0 = q0 + mrow;
        const int row1 = row0 + 8;
        if (k0 + 63 > row0) {
#pragma unroll
            for (int nt = 0; nt < 8; ++nt) {
                int c0 = k0 + nt * 8 + 2 * tig;
                if (c0 > row0) Sacc[nt][0] = -1e30f;
                if (c0 + 1 > row0) Sacc[nt][1] = -1e30f;
                if (c0 > row1) Sacc[nt][2] = -1e30f;
                if (c0 + 1 > row1) Sacc[nt][3] = -1e30f;
            }
        }

        // ---- online softmax ----
        float mx0 = -1e30f, mx1 = -1e30f;
#pragma unroll
        for (int nt = 0; nt < 8; ++nt) {
            mx0 = fmaxf(mx0, fmaxf(Sacc[nt][0], Sacc[nt][1]));
            mx1 = fmaxf(mx1, fmaxf(Sacc[nt][2], Sacc[nt][3]));
        }
        mx0 = fmaxf(mx0, __shfl_xor_sync(0xffffffffu, mx0, 1));
        mx0 = fmaxf(mx0, __shfl_xor_sync(0xffffffffu, mx0, 2));
        mx1 = fmaxf(mx1, __shfl_xor_sync(0xffffffffu, mx1, 1));
        mx1 = fmaxf(mx1, __shfl_xor_sync(0xffffffffu, mx1, 2));

        float mn0 = fmaxf(m_i[0], mx0);
        float mn1 = fmaxf(m_i[1], mx1);
        float a0 = __expf(m_i[0] - mn0);
        float a1 = __expf(m_i[1] - mn1);

        float ps0 = 0.f, ps1 = 0.f;
#pragma unroll
        for (int nt = 0; nt < 8; ++nt) {
            float p00 = __expf(Sacc[nt][0] - mn0);
            float p01 = __expf(Sacc[nt][1] - mn0);
            float p10 = __expf(Sacc[nt][2] - mn1);
            float p11 = __expf(Sacc[nt][3] - mn1);
            ps0 += p00 + p01;
            ps1 += p10 + p11;
            *reinterpret_cast<float2*>(&Ps[(mrow) * FP + nt * 8 + 2 * tig]) =
                make_float2(p00, p01);
            *reinterpret_cast<float2*>(&Ps[(mrow + 8) * FP + nt * 8 + 2 * tig]) =
                make_float2(p10, p11);
        }
        ps0 += __shfl_xor_sync(0xffffffffu, ps0, 1);
        ps0 += __shfl_xor_sync(0xffffffffu, ps0, 2);
        ps1 += __shfl_xor_sync(0xffffffffu, ps1, 1);
        ps1 += __shfl_xor_sync(0xffffffffu, ps1, 2);

        l_i[0] = l_i[0] * a0 + ps0;
        l_i[1] = l_i[1] * a1 + ps1;
        m_i[0] = mn0;
        m_i[1] = mn1;
#pragma unroll
        for (int nt = 0; nt < 8; ++nt) {
            Oacc[nt][0] *= a0;
            Oacc[nt][1] *= a0;
            Oacc[nt][2] *= a1;
            Oacc[nt][3] *= a1;
        }
        __syncwarp();   // P rows are warp-private

        // ---- O += P V ----
        const float* Vb = Vs + buf * 64 * VP;
#pragma unroll
        for (int kk = 0; kk < 64; kk += 8) {
            unsigned af[4];
            af[0] = f2tf32(Ps[(mrow) * FP + kk + tig]);
            af[1] = f2tf32(Ps[(mrow + 8) * FP + kk + tig]);
            af[2] = f2tf32(Ps[(mrow) * FP + kk + tig + 4]);
            af[3] = f2tf32(Ps[(mrow + 8) * FP + kk + tig + 4]);
#pragma unroll
            for (int nt = 0; nt < 8; ++nt) {
                unsigned bf[2];
                bf[0] = f2tf32(Vb[(kk + tig) * VP + nt * 8 + gid]);
                bf[1] = f2tf32(Vb[(kk + tig + 4) * VP + nt * 8 + gid]);
                mma_tf32(Oacc[nt], af, bf);
            }
        }
        buf ^= 1;
    }

    // ---- normalize + write token-major ----
    float inv0 = 1.0f / l_i[0];
    float inv1 = 1.0f / l_i[1];
    const int row0 = q0 + mrow;
    const int row1 = row0 + 8;
#pragma unroll
    for (int nt = 0; nt < 8; ++nt) {
        int col = h * DK_ + nt * 8 + 2 * tig;
        *reinterpret_cast<float2*>(&g_attn[((size_t)(b * S_ + row0)) * D_ + col]) =
            make_float2(Oacc[nt][0] * inv0, Oacc[nt][1] * inv0);
        *reinterpret_cast<float2*>(&g_attn[((size_t)(b * S_ + row1)) * D_ + col]) =
            make_float2(Oacc[nt][2] * inv1, Oacc[nt][3] * inv1);
    }
}

// ---------------------------------------------------------------------------
extern "C" void kernel_launch(void* const* d_in, const int* in_sizes, int n_in,
                              void* d_out, int out_size) {
    const float* x = (const float*)d_in[0];
    const int* pos = (const int*)d_in[1];
    const float* wq = (const float*)d_in[2];
    const float* wk = (const float*)d_in[3];
    const float* wv = (const float*)d_in[4];
    const float* wo = (const float*)d_in[5];
    float* out = (float*)d_out;

    float *qp, *kp, *vp, *attnp;
    cudaGetSymbolAddress((void**)&qp, g_q);
    cudaGetSymbolAddress((void**)&kp, g_k);
    cudaGetSymbolAddress((void**)&vp, g_v);
    cudaGetSymbolAddress((void**)&attnp, g_attn);

    static bool attr_done = false;
    if (!attr_done) {
        cudaFuncSetAttribute(gemm_qkv_kernel,
                             cudaFuncAttributeMaxDynamicSharedMemorySize, GEMM_SMEM);
        cudaFuncSetAttribute(gemm_out_kernel,
                             cudaFuncAttributeMaxDynamicSharedMemorySize, GEMM_SMEM);
        cudaFuncSetAttribute(flash_tf32_kernel,
                             cudaFuncAttributeMaxDynamicSharedMemorySize, FLASH_SMEM);
        attr_done = true;
    }

    // RoPE cos/sin table (fp32 trig; angle computed in fp32 as before).
    rope_table_kernel<<<(B_ * S_ * 32) / 256, 256>>>(pos);

    dim3 qkv_grid(D_ / 128, M_ / 128, 3);   // (8, 32, 3)
    gemm_qkv_kernel<<<qkv_grid, 256, GEMM_SMEM>>>(x, wq, wk, wv, qp, kp, vp);

    dim3 flash_grid(S_ / 64, B_ * H_);      // (32, 32)
    flash_tf32_kernel<<<flash_grid, 128, FLASH_SMEM>>>();

    dim3 gemm_grid(D_ / 128, M_ / 128);     // (8, 32)
    gemm_out_kernel<<<gemm_grid, 256, GEMM_SMEM>>>(attnp, wo, out);
}

// round 8
// speedup vs baseline: 1.2945x; 1.1313x over previous
#include <cuda_runtime.h>
#include <math.h>

// Problem constants (fixed by the reference).
#define B_ 2
#define S_ 2048
#define D_ 1024
#define H_ 16
#define DK_ 64
#define M_ (B_ * S_)   // 4096 token rows

// Scratch (allocation-free rule: __device__ globals).
__device__ float g_q[B_ * H_ * S_ * DK_];     // [b,h,s,d]  tf32-grid values
__device__ float g_k[B_ * H_ * S_ * DK_];     // tf32-grid
__device__ float g_v[B_ * H_ * S_ * DK_];     // tf32-grid
__device__ float g_attn[M_ * D_];             // [b,s,h*dk] tf32-grid
__device__ float2 g_rope[B_ * S_ * 32];       // (cos,sin) per (b,s,pair)
__device__ float g_xf[M_ * D_];               // x rounded to tf32 grid
__device__ float g_wf[4 * D_ * D_];           // wq,wk,wv,wo rounded to tf32 grid

// ---------------------------------------------------------------------------
// tf32 / cp.async / ldmatrix helpers
// ---------------------------------------------------------------------------
__device__ __forceinline__ unsigned f2tf32(float f) {
    unsigned u;
    asm("cvt.rna.tf32.f32 %0, %1;" : "=r"(u) : "f"(f));
    return u;
}
__device__ __forceinline__ float tf32r(float f) {   // round to tf32 grid, as float
    return __uint_as_float(f2tf32(f));
}

__device__ __forceinline__ void mma_tf32(float (&c)[4], const unsigned (&a)[4],
                                         const unsigned (&b)[2]) {
    asm volatile(
        "mma.sync.aligned.m16n8k8.row.col.f32.tf32.tf32.f32 "
        "{%0,%1,%2,%3}, {%4,%5,%6,%7}, {%8,%9}, {%0,%1,%2,%3};\n"
        : "+f"(c[0]), "+f"(c[1]), "+f"(c[2]), "+f"(c[3])
        : "r"(a[0]), "r"(a[1]), "r"(a[2]), "r"(a[3]), "r"(b[0]), "r"(b[1]));
}

__device__ __forceinline__ void cp_async16(void* smem, const void* gmem) {
    unsigned saddr = (unsigned)__cvta_generic_to_shared(smem);
    asm volatile("cp.async.cg.shared.global [%0], [%1], 16;\n" ::"r"(saddr),
                 "l"(gmem));
}
__device__ __forceinline__ void cp_commit() {
    asm volatile("cp.async.commit_group;\n");
}
template <int N>
__device__ __forceinline__ void cp_wait() {
    asm volatile("cp.async.wait_group %0;\n" ::"n"(N));
}

// ldmatrix on 32-bit data: each m8n8.b16 "matrix" = an 8x4 tile of b32;
// thread T receives element (row T/4, col T%4) — exactly the (gid,tig)
// mapping of m16n8k8 tf32 fragments.
__device__ __forceinline__ void ldsm_x4(unsigned (&r)[4], unsigned saddr) {
    asm volatile(
        "ldmatrix.sync.aligned.m8n8.x4.shared.b16 {%0,%1,%2,%3}, [%4];"
        : "=r"(r[0]), "=r"(r[1]), "=r"(r[2]), "=r"(r[3])
        : "r"(saddr));
}
__device__ __forceinline__ void ldsm_x2(unsigned (&r)[2], unsigned saddr) {
    asm volatile("ldmatrix.sync.aligned.m8n8.x2.shared.b16 {%0,%1}, [%2];"
                 : "=r"(r[0]), "=r"(r[1])
                 : "r"(saddr));
}

// ---------------------------------------------------------------------------
// Prep: round x and the four weight matrices to the tf32 grid (once).
// grid (4096, 5) x 256 threads, float4 per thread.
// ---------------------------------------------------------------------------
__global__ void cvt_tf32_kernel(const float* __restrict__ x,
                                const float* __restrict__ wq,
                                const float* __restrict__ wk,
                                const float* __restrict__ wv,
                                const float* __restrict__ wo) {
    const int z = blockIdx.y;
    const float* src;
    float* dst;
    int n;
    if (z == 0) { src = x; dst = g_xf; n = M_ * D_; }
    else {
        src = (z == 1) ? wq : (z == 2) ? wk : (z == 3) ? wv : wo;
        dst = g_wf + (size_t)(z - 1) * D_ * D_;
        n = D_ * D_;
    }
    int i = (blockIdx.x * 256 + threadIdx.x) * 4;
    if (i >= n) return;
    float4 v = *reinterpret_cast<const float4*>(src + i);
    v.x = tf32r(v.x); v.y = tf32r(v.y); v.z = tf32r(v.z); v.w = tf32r(v.w);
    *reinterpret_cast<float4*>(dst + i) = v;
}

// ---------------------------------------------------------------------------
// RoPE table: g_rope[(b*S+s)*32 + j] = (cos, sin).
// ---------------------------------------------------------------------------
__global__ void rope_table_kernel(const int* __restrict__ pos) {
    int t = blockIdx.x * blockDim.x + threadIdx.x;   // 131072 threads
    int j = t & 31;
    int s = (t >> 5) & (S_ - 1);
    int b = t >> 16;
    float p = (float)pos[b * S_ + s];
    float freq = powf(10000.0f, -((float)(2 * j) / 64.0f));
    float ang = p * freq;
    float sv, cv;
    sincosf(ang, &sv, &cv);
    g_rope[t] = make_float2(cv, sv);
}

// ---------------------------------------------------------------------------
// tf32 GEMM body (NT): C[m,n] = sum_k A[m,k] * W[n,k].
// A and W are ALREADY on the tf32 grid. Tile 128x128, BK=32, 256 threads,
// 8 warps (2m x 4n), warp tile 64x32. 3-stage cp.async pipeline, one barrier
// per K-iter. Fragments gathered with ldmatrix (no cvt, no scalar LDS).
// MODE 0: plain write, MODE 1: [b,h,s,d] scatter (tf32-rounded),
// MODE 2: scatter + RoPE(table) (tf32-rounded)
// ---------------------------------------------------------------------------
#define GSTRIDE 36
#define STAGE_FLOATS (2 * 128 * GSTRIDE)
#define GEMM_SMEM (3 * STAGE_FLOATS * 4)   // 110592 B

template <int MODE>
__device__ __forceinline__ void gemm_body(
    float* sm, const float* __restrict__ A, const float* __restrict__ W,
    float* __restrict__ Cout) {
    const int tid = threadIdx.x;
    const int lane = tid & 31;
    const int warp = tid >> 5;
    const int wr = warp >> 2;
    const int wc = warp & 3;
    const int m0 = blockIdx.y * 128;
    const int n0 = blockIdx.x * 128;
    const int gid = lane >> 2;
    const int tig = lane & 3;
    const int sub = lane >> 3;       // 0..3 (ldmatrix tile index)
    const int rowin = lane & 7;      // row within 8-row tile

    const float* Ab = A + (size_t)m0 * D_;
    const float* Wb = W + (size_t)n0 * D_;
    const unsigned sbase = (unsigned)__cvta_generic_to_shared(sm);

    float acc[4][4][4];
#pragma unroll
    for (int i = 0; i < 4; ++i)
#pragma unroll
        for (int j = 0; j < 4; ++j)
#pragma unroll
            for (int r = 0; r < 4; ++r) acc[i][j][r] = 0.0f;

    auto issue = [&](int st, int k0) {
        float(*As)[GSTRIDE] =
            reinterpret_cast<float(*)[GSTRIDE]>(sm + st * STAGE_FLOATS);
        float(*Bs)[GSTRIDE] = reinterpret_cast<float(*)[GSTRIDE]>(
            sm + st * STAGE_FLOATS + 128 * GSTRIDE);
#pragma unroll
        for (int i = 0; i < 4; ++i) {
            int l = tid + i * 256;
            int r = l >> 3;
            int c = (l & 7) << 2;
            cp_async16(&As[r][c], Ab + (size_t)r * D_ + k0 + c);
            cp_async16(&Bs[r][c], Wb + (size_t)r * D_ + k0 + c);
        }
        cp_commit();
    };

    // ldmatrix row/col offsets (bytes), constant per thread:
    // A tile (mt,kk): row = wr*64 + mt*16 + (sub&1)*8 + rowin, col = kk + (sub>>1)*4
    // B tile (nt,kk): row = wc*32 + nt*8 + rowin,             col = kk + (sub&1)*4
    const int arow = wr * 64 + (sub & 1) * 8 + rowin;
    const int acol = (sub >> 1) * 4;
    const int brow = wc * 32 + rowin;
    const int bcol = (sub & 1) * 4;

    const int NIT = D_ / 32;
    issue(0, 0);
    issue(1, 32);
    int st = 0;
    for (int it = 0; it < NIT; ++it) {
        if (it + 1 < NIT) {
            cp_wait<1>();
        } else {
            cp_wait<0>();
        }
        __syncthreads();

        if (it + 2 < NIT) issue((st + 2) % 3, (it + 2) * 32);

        const unsigned aoff = sbase + st * (STAGE_FLOATS * 4);
        const unsigned boff = aoff + 128 * GSTRIDE * 4;

#pragma unroll
        for (int kk = 0; kk < 32; kk += 8) {
            unsigned af[4][4], bf[4][2];
#pragma unroll
            for (int mt = 0; mt < 4; ++mt)
                ldsm_x4(af[mt],
                        aoff + ((arow + mt * 16) * GSTRIDE + kk + acol) * 4);
#pragma unroll
            for (int nt = 0; nt < 4; ++nt)
                ldsm_x2(bf[nt],
                        boff + ((brow + nt * 8) * GSTRIDE + kk + bcol) * 4);
#pragma unroll
            for (int mt = 0; mt < 4; ++mt)
#pragma unroll
                for (int nt = 0; nt < 4; ++nt) mma_tf32(acc[mt][nt], af[mt], bf[nt]);
        }
        st = (st + 1) % 3;
    }

    // ---------------- Epilogue ----------------
#pragma unroll
    for (int mt = 0; mt < 4; ++mt) {
        int row0 = m0 + wr * 64 + mt * 16 + gid;
        int b0i = row0 >> 11, s0i = row0 & (S_ - 1);
        int row1 = row0 + 8;
        int b1i = row1 >> 11, s1i = row1 & (S_ - 1);

#pragma unroll
        for (int nt = 0; nt < 4; ++nt) {
            int col = n0 + wc * 32 + nt * 8 + 2 * tig;
            float e0 = acc[mt][nt][0], o0 = acc[mt][nt][1];
            float e1 = acc[mt][nt][2], o1 = acc[mt][nt][3];

            if (MODE == 2) {
                int j = (col & 63) >> 1;
                float2 cs0 = g_rope[(size_t)(b0i * S_ + s0i) * 32 + j];
                float2 cs1 = g_rope[(size_t)(b1i * S_ + s1i) * 32 + j];
                float re0 = e0 * cs0.x - o0 * cs0.y;
                float ro0 = e0 * cs0.y + o0 * cs0.x;
                float re1 = e1 * cs1.x - o1 * cs1.y;
                float ro1 = e1 * cs1.y + o1 * cs1.x;
                e0 = re0; o0 = ro0; e1 = re1; o1 = ro1;
            }

            if (MODE == 0) {
                *reinterpret_cast<float2*>(Cout + (size_t)row0 * D_ + col) =
                    make_float2(e0, o0);
                *reinterpret_cast<float2*>(Cout + (size_t)row1 * D_ + col) =
                    make_float2(e1, o1);
            } else {
                // Store rounded to the tf32 grid (consumer reads raw).
                int h = col >> 6;
                int d = col & 63;
                *reinterpret_cast<float2*>(
                    Cout + (((size_t)(b0i * H_ + h) * S_ + s0i) * DK_ + d)) =
                    make_float2(tf32r(e0), tf32r(o0));
                *reinterpret_cast<float2*>(
                    Cout + (((size_t)(b1i * H_ + h) * S_ + s1i) * DK_ + d)) =
                    make_float2(tf32r(e1), tf32r(o1));
            }
        }
    }
}

// Merged Q/K/V projection: blockIdx.z selects weight + destination + mode.
__global__ void __launch_bounds__(256, 2) gemm_qkv_kernel(
    float* __restrict__ qp, float* __restrict__ kp, float* __restrict__ vp) {
    extern __shared__ float sm[];
    const int z = blockIdx.z;
    if (z == 0)      gemm_body<2>(sm, g_xf, g_wf, qp);
    else if (z == 1) gemm_body<2>(sm, g_xf, g_wf + (size_t)D_ * D_, kp);
    else             gemm_body<1>(sm, g_xf, g_wf + (size_t)2 * D_ * D_, vp);
}

// Output projection.
__global__ void __launch_bounds__(256, 2) gemm_out_kernel(
    const float* __restrict__ A, float* __restrict__ Cout) {
    extern __shared__ float sm[];
    gemm_body<0>(sm, A, g_wf + (size_t)3 * D_ * D_, Cout);
}

// ---------------------------------------------------------------------------
// Flash attention, tf32 tensor cores, causal. BM=64 q-rows/CTA, 128 threads
// (4 warps x 16 rows), 2 CTAs/SM. K/V/Q arrive already on the tf32 grid, so
// the inner loops have NO cvt — raw bit loads feed the mma.
// ---------------------------------------------------------------------------
#define FP 68
#define VP 72
#define FLASH_SMEM ((64 * FP + 2 * 64 * FP + 2 * 64 * VP + 64 * FP) * 4)

__global__ void __launch_bounds__(128, 2) flash_tf32_kernel() {
    extern __shared__ float smf[];
    float* Qs = smf;                            // [64][FP]
    float* Ks = Qs + 64 * FP;                   // [2][64][FP]
    float* Vs = Ks + 2 * 64 * FP;               // [2][64][VP]
    float* Ps = Vs + 2 * 64 * VP;               // [64][FP]

    const int qb = gridDim.x - 1 - blockIdx.x;  // long blocks first
    const int bh = blockIdx.y;
    const int b = bh >> 4;
    const int h = bh & 15;

    const float* Qp = g_q + (size_t)bh * S_ * DK_;
    const float* Kp = g_k + (size_t)bh * S_ * DK_;
    const float* Vp = g_v + (size_t)bh * S_ * DK_;

    const int tid = threadIdx.x;
    const int lane = tid & 31;
    const int warp = tid >> 5;                  // 0..3
    const int gid = lane >> 2;
    const int tig = lane & 3;
    const int q0 = qb * 64;
    const int mrow = warp * 16 + gid;           // 0..63

    // Load Q tile: x 0.125 (exact on tf32-grid values -> stays on grid).
#pragma unroll
    for (int i = 0; i < 8; ++i) {
        int l = tid + i * 128;
        int r = l >> 4;
        int c = (l & 15) << 2;
        float4 v = *reinterpret_cast<const float4*>(Qp + (size_t)(q0 + r) * DK_ + c);
        Qs[r * FP + c + 0] = v.x * 0.125f;
        Qs[r * FP + c + 1] = v.y * 0.125f;
        Qs[r * FP + c + 2] = v.z * 0.125f;
        Qs[r * FP + c + 3] = v.w * 0.125f;
    }

    auto issueKV = [&](int bf, int k0) {
#pragma unroll
        for (int i = 0; i < 8; ++i) {
            int l = tid + i * 128;
            int r = l >> 4;
            int c = (l & 15) << 2;
            cp_async16(Ks + bf * 64 * FP + r * FP + c,
                       Kp + (size_t)(k0 + r) * DK_ + c);
            cp_async16(Vs + bf * 64 * VP + r * VP + c,
                       Vp + (size_t)(k0 + r) * DK_ + c);
        }
        cp_commit();
    };

    issueKV(0, 0);

    float m_i[2] = {-1e30f, -1e30f};
    float l_i[2] = {0.f, 0.f};
    float Oacc[8][4];
#pragma unroll
    for (int nt = 0; nt < 8; ++nt)
#pragma unroll
        for (int r = 0; r < 4; ++r) Oacc[nt][r] = 0.0f;

    const int ntiles = qb + 1;
    int buf = 0;
    for (int kb = 0; kb < ntiles; ++kb) {
        const int k0 = kb * 64;
        cp_wait<0>();
        __syncthreads();
        if (kb + 1 < ntiles) issueKV(buf ^ 1, k0 + 64);

        // ---- S = Q K^T ----
        const float* Kb = Ks + buf * 64 * FP;
        float Sacc[8][4];
#pragma unroll
        for (int nt = 0; nt < 8; ++nt)
#pragma unroll
            for (int r = 0; r < 4; ++r) Sacc[nt][r] = 0.0f;

#pragma unroll
        for (int kk = 0; kk < 64; kk += 8) {
            unsigned af[4];
            af[0] = __float_as_uint(Qs[(mrow) * FP + kk + tig]);
            af[1] = __float_as_uint(Qs[(mrow + 8) * FP + kk + tig]);
            af[2] = __float_as_uint(Qs[(mrow) * FP + kk + tig + 4]);
            af[3] = __float_as_uint(Qs[(mrow + 8) * FP + kk + tig + 4]);
#pragma unroll
            for (int nt = 0; nt < 8; ++nt) {
                unsigned bf[2];
                bf[0] = __float_as_uint(Kb[(nt * 8 + gid) * FP + kk + tig]);
                bf[1] = __float_as_uint(Kb[(nt * 8 + gid) * FP + kk + tig + 4]);
                mma_tf32(Sacc[nt], af, bf);
            }
        }

        // ---- causal mask ----
        const int row0 = q0 + mrow;
        const int row1 = row0 + 8;
        if (k0 + 63 > row0) {
#pragma unroll
            for (int nt = 0; nt < 8; ++nt) {
                int c0 = k0 + nt * 8 + 2 * tig;
                if (c0 > row0) Sacc[nt][0] = -1e30f;
                if (c0 + 1 > row0) Sacc[nt][1] = -1e30f;
                if (c0 > row1) Sacc[nt][2] = -1e30f;
                if (c0 + 1 > row1) Sacc[nt][3] = -1e30f;
            }
        }

        // ---- online softmax ----
        float mx0 = -1e30f, mx1 = -1e30f;
#pragma unroll
        for (int nt = 0; nt < 8; ++nt) {
            mx0 = fmaxf(mx0, fmaxf(Sacc[nt][0], Sacc[nt][1]));
            mx1 = fmaxf(mx1, fmaxf(Sacc[nt][2], Sacc[nt][3]));
        }
        mx0 = fmaxf(mx0, __shfl_xor_sync(0xffffffffu, mx0, 1));
        mx0 = fmaxf(mx0, __shfl_xor_sync(0xffffffffu, mx0, 2));
        mx1 = fmaxf(mx1, __shfl_xor_sync(0xffffffffu, mx1, 1));
        mx1 = fmaxf(mx1, __shfl_xor_sync(0xffffffffu, mx1, 2));

        float mn0 = fmaxf(m_i[0], mx0);
        float mn1 = fmaxf(m_i[1], mx1);
        float a0 = __expf(m_i[0] - mn0);
        float a1 = __expf(m_i[1] - mn1);

        float ps0 = 0.f, ps1 = 0.f;
#pragma unroll
        for (int nt = 0; nt < 8; ++nt) {
            float p00 = __expf(Sacc[nt][0] - mn0);
            float p01 = __expf(Sacc[nt][1] - mn0);
            float p10 = __expf(Sacc[nt][2] - mn1);
            float p11 = __expf(Sacc[nt][3] - mn1);
            ps0 += p00 + p01;
            ps1 += p10 + p11;
            *reinterpret_cast<float2*>(&Ps[(mrow) * FP + nt * 8 + 2 * tig]) =
                make_float2(p00, p01);
            *reinterpret_cast<float2*>(&Ps[(mrow + 8) * FP + nt * 8 + 2 * tig]) =
                make_float2(p10, p11);
        }
        ps0 += __shfl_xor_sync(0xffffffffu, ps0, 1);
        ps0 += __shfl_xor_sync(0xffffffffu, ps0, 2);
        ps1 += __shfl_xor_sync(0xffffffffu, ps1, 1);
        ps1 += __shfl_xor_sync(0xffffffffu, ps1, 2);

        l_i[0] = l_i[0] * a0 + ps0;
        l_i[1] = l_i[1] * a1 + ps1;
        m_i[0] = mn0;
        m_i[1] = mn1;
#pragma unroll
        for (int nt = 0; nt < 8; ++nt) {
            Oacc[nt][0] *= a0;
            Oacc[nt][1] *= a0;
            Oacc[nt][2] *= a1;
            Oacc[nt][3] *= a1;
        }
        __syncwarp();   // P rows are warp-private

        // ---- O += P V ----
        const float* Vb = Vs + buf * 64 * VP;
#pragma unroll
        for (int kk = 0; kk < 64; kk += 8) {
            unsigned af[4];
            af[0] = f2tf32(Ps[(mrow) * FP + kk + tig]);
            af[1] = f2tf32(Ps[(mrow + 8) * FP + kk + tig]);
            af[2] = f2tf32(Ps[(mrow) * FP + kk + tig + 4]);
            af[3] = f2tf32(Ps[(mrow + 8) * FP + kk + tig + 4]);
#pragma unroll
            for (int nt = 0; nt < 8; ++nt) {
                unsigned bf[2];
                bf[0] = __float_as_uint(Vb[(kk + tig) * VP + nt * 8 + gid]);
                bf[1] = __float_as_uint(Vb[(kk + tig + 4) * VP + nt * 8 + gid]);
                mma_tf32(Oacc[nt], af, bf);
            }
        }
        buf ^= 1;
    }

    // ---- normalize + write token-major (rounded to tf32 grid) ----
    float inv0 = 1.0f / l_i[0];
    float inv1 = 1.0f / l_i[1];
    const int row0 = q0 + mrow;
    const int row1 = row0 + 8;
#pragma unroll
    for (int nt = 0; nt < 8; ++nt) {
        int col = h * DK_ + nt * 8 + 2 * tig;
        *reinterpret_cast<float2*>(&g_attn[((size_t)(b * S_ + row0)) * D_ + col]) =
            make_float2(tf32r(Oacc[nt][0] * inv0), tf32r(Oacc[nt][1] * inv0));
        *reinterpret_cast<float2*>(&g_attn[((size_t)(b * S_ + row1)) * D_ + col]) =
            make_float2(tf32r(Oacc[nt][2] * inv1), tf32r(Oacc[nt][3] * inv1));
    }
}

// ---------------------------------------------------------------------------
extern "C" void kernel_launch(void* const* d_in, const int* in_sizes, int n_in,
                              void* d_out, int out_size) {
    const float* x = (const float*)d_in[0];
    const int* pos = (const int*)d_in[1];
    const float* wq = (const float*)d_in[2];
    const float* wk = (const float*)d_in[3];
    const float* wv = (const float*)d_in[4];
    const float* wo = (const float*)d_in[5];
    float* out = (float*)d_out;

    float *qp, *kp, *vp, *attnp;
    cudaGetSymbolAddress((void**)&qp, g_q);
    cudaGetSymbolAddress((void**)&kp, g_k);
    cudaGetSymbolAddress((void**)&vp, g_v);
    cudaGetSymbolAddress((void**)&attnp, g_attn);

    static bool attr_done = false;
    if (!attr_done) {
        cudaFuncSetAttribute(gemm_qkv_kernel,
                             cudaFuncAttributeMaxDynamicSharedMemorySize, GEMM_SMEM);
        cudaFuncSetAttribute(gemm_out_kernel,
                             cudaFuncAttributeMaxDynamicSharedMemorySize, GEMM_SMEM);
        cudaFuncSetAttribute(flash_tf32_kernel,
                             cudaFuncAttributeMaxDynamicSharedMemorySize, FLASH_SMEM);
        attr_done = true;
    }

    // Prep: tf32-round x and weights; RoPE cos/sin table.
    dim3 cvt_grid(M_ * D_ / 4 / 256, 5);
    cvt_tf32_kernel<<<cvt_grid, 256>>>(x, wq, wk, wv, wo);
    rope_table_kernel<<<(B_ * S_ * 32) / 256, 256>>>(pos);

    dim3 qkv_grid(D_ / 128, M_ / 128, 3);   // (8, 32, 3)
    gemm_qkv_kernel<<<qkv_grid, 256, GEMM_SMEM>>>(qp, kp, vp);

    dim3 flash_grid(S_ / 64, B_ * H_);      // (32, 32)
    flash_tf32_kernel<<<flash_grid, 128, FLASH_SMEM>>>();

    dim3 gemm_grid(D_ / 128, M_ / 128);     // (8, 32)
    gemm_out_kernel<<<gemm_grid, 256, GEMM_SMEM>>>(attnp, out);
}

// round 9
// speedup vs baseline: 1.3000x; 1.0043x over previous
#include <cuda_runtime.h>
#include <math.h>

// Problem constants (fixed by the reference).
#define B_ 2
#define S_ 2048
#define D_ 1024
#define H_ 16
#define DK_ 64
#define M_ (B_ * S_)   // 4096 token rows

// Scratch (allocation-free rule: __device__ globals).
__device__ float g_q[B_ * H_ * S_ * DK_];     // [b,h,s,d]  tf32-grid values
__device__ float g_k[B_ * H_ * S_ * DK_];     // tf32-grid
__device__ float g_v[B_ * H_ * S_ * DK_];     // tf32-grid
__device__ float g_attn[M_ * D_];             // [b,s,h*dk] tf32-grid
__device__ float2 g_rope[B_ * S_ * 32];       // (cos,sin) per (b,s,pair)
__device__ float g_xf[M_ * D_];               // x rounded to tf32 grid
__device__ float g_wf[4 * D_ * D_];           // wq,wk,wv,wo rounded to tf32 grid

// ---------------------------------------------------------------------------
// tf32 / cp.async / ldmatrix helpers
// ---------------------------------------------------------------------------
__device__ __forceinline__ unsigned f2tf32(float f) {
    unsigned u;
    asm("cvt.rna.tf32.f32 %0, %1;" : "=r"(u) : "f"(f));
    return u;
}
__device__ __forceinline__ float tf32r(float f) {   // round to tf32 grid, as float
    return __uint_as_float(f2tf32(f));
}

__device__ __forceinline__ void mma_tf32(float (&c)[4], const unsigned (&a)[4],
                                         const unsigned (&b)[2]) {
    asm volatile(
        "mma.sync.aligned.m16n8k8.row.col.f32.tf32.tf32.f32 "
        "{%0,%1,%2,%3}, {%4,%5,%6,%7}, {%8,%9}, {%0,%1,%2,%3};\n"
        : "+f"(c[0]), "+f"(c[1]), "+f"(c[2]), "+f"(c[3])
        : "r"(a[0]), "r"(a[1]), "r"(a[2]), "r"(a[3]), "r"(b[0]), "r"(b[1]));
}
__device__ __forceinline__ void mma_tf32b(float (&c)[4], const unsigned (&a)[4],
                                          unsigned b0, unsigned b1) {
    asm volatile(
        "mma.sync.aligned.m16n8k8.row.col.f32.tf32.tf32.f32 "
        "{%0,%1,%2,%3}, {%4,%5,%6,%7}, {%8,%9}, {%0,%1,%2,%3};\n"
        : "+f"(c[0]), "+f"(c[1]), "+f"(c[2]), "+f"(c[3])
        : "r"(a[0]), "r"(a[1]), "r"(a[2]), "r"(a[3]), "r"(b0), "r"(b1));
}

__device__ __forceinline__ void cp_async16(void* smem, const void* gmem) {
    unsigned saddr = (unsigned)__cvta_generic_to_shared(smem);
    asm volatile("cp.async.cg.shared.global [%0], [%1], 16;\n" ::"r"(saddr),
                 "l"(gmem));
}
__device__ __forceinline__ void cp_commit() {
    asm volatile("cp.async.commit_group;\n");
}
template <int N>
__device__ __forceinline__ void cp_wait() {
    asm volatile("cp.async.wait_group %0;\n" ::"n"(N));
}

// ldmatrix on 32-bit data: each m8n8.b16 "matrix" = an 8x4 tile of b32;
// thread T receives element (row T/4, col T%4) of tile i in reg i.
__device__ __forceinline__ void ldsm_x4(unsigned (&r)[4], unsigned saddr) {
    asm volatile(
        "ldmatrix.sync.aligned.m8n8.x4.shared.b16 {%0,%1,%2,%3}, [%4];"
        : "=r"(r[0]), "=r"(r[1]), "=r"(r[2]), "=r"(r[3])
        : "r"(saddr));
}
__device__ __forceinline__ void ldsm_x2(unsigned (&r)[2], unsigned saddr) {
    asm volatile("ldmatrix.sync.aligned.m8n8.x2.shared.b16 {%0,%1}, [%2];"
                 : "=r"(r[0]), "=r"(r[1])
                 : "r"(saddr));
}

// ---------------------------------------------------------------------------
// Prep: round x and the four weight matrices to the tf32 grid (once).
// ---------------------------------------------------------------------------
__global__ void cvt_tf32_kernel(const float* __restrict__ x,
                                const float* __restrict__ wq,
                                const float* __restrict__ wk,
                                const float* __restrict__ wv,
                                const float* __restrict__ wo) {
    const int z = blockIdx.y;
    const float* src;
    float* dst;
    int n;
    if (z == 0) { src = x; dst = g_xf; n = M_ * D_; }
    else {
        src = (z == 1) ? wq : (z == 2) ? wk : (z == 3) ? wv : wo;
        dst = g_wf + (size_t)(z - 1) * D_ * D_;
        n = D_ * D_;
    }
    int i = (blockIdx.x * 256 + threadIdx.x) * 4;
    if (i >= n) return;
    float4 v = *reinterpret_cast<const float4*>(src + i);
    v.x = tf32r(v.x); v.y = tf32r(v.y); v.z = tf32r(v.z); v.w = tf32r(v.w);
    *reinterpret_cast<float4*>(dst + i) = v;
}

// ---------------------------------------------------------------------------
// RoPE table: g_rope[(b*S+s)*32 + j] = (cos, sin).
// ---------------------------------------------------------------------------
__global__ void rope_table_kernel(const int* __restrict__ pos) {
    int t = blockIdx.x * blockDim.x + threadIdx.x;   // 131072 threads
    int j = t & 31;
    int s = (t >> 5) & (S_ - 1);
    int b = t >> 16;
    float p = (float)pos[b * S_ + s];
    float freq = powf(10000.0f, -((float)(2 * j) / 64.0f));
    float ang = p * freq;
    float sv, cv;
    sincosf(ang, &sv, &cv);
    g_rope[t] = make_float2(cv, sv);
}

// ---------------------------------------------------------------------------
// tf32 GEMM body (NT): C[m,n] = sum_k A[m,k] * W[n,k].  (unchanged from R7)
// ---------------------------------------------------------------------------
#define GSTRIDE 36
#define STAGE_FLOATS (2 * 128 * GSTRIDE)
#define GEMM_SMEM (3 * STAGE_FLOATS * 4)   // 110592 B

template <int MODE>
__device__ __forceinline__ void gemm_body(
    float* sm, const float* __restrict__ A, const float* __restrict__ W,
    float* __restrict__ Cout) {
    const int tid = threadIdx.x;
    const int lane = tid & 31;
    const int warp = tid >> 5;
    const int wr = warp >> 2;
    const int wc = warp & 3;
    const int m0 = blockIdx.y * 128;
    const int n0 = blockIdx.x * 128;
    const int gid = lane >> 2;
    const int tig = lane & 3;
    const int sub = lane >> 3;
    const int rowin = lane & 7;

    const float* Ab = A + (size_t)m0 * D_;
    const float* Wb = W + (size_t)n0 * D_;
    const unsigned sbase = (unsigned)__cvta_generic_to_shared(sm);

    float acc[4][4][4];
#pragma unroll
    for (int i = 0; i < 4; ++i)
#pragma unroll
        for (int j = 0; j < 4; ++j)
#pragma unroll
            for (int r = 0; r < 4; ++r) acc[i][j][r] = 0.0f;

    auto issue = [&](int st, int k0) {
        float(*As)[GSTRIDE] =
            reinterpret_cast<float(*)[GSTRIDE]>(sm + st * STAGE_FLOATS);
        float(*Bs)[GSTRIDE] = reinterpret_cast<float(*)[GSTRIDE]>(
            sm + st * STAGE_FLOATS + 128 * GSTRIDE);
#pragma unroll
        for (int i = 0; i < 4; ++i) {
            int l = tid + i * 256;
            int r = l >> 3;
            int c = (l & 7) << 2;
            cp_async16(&As[r][c], Ab + (size_t)r * D_ + k0 + c);
            cp_async16(&Bs[r][c], Wb + (size_t)r * D_ + k0 + c);
        }
        cp_commit();
    };

    const int arow = wr * 64 + (sub & 1) * 8 + rowin;
    const int acol = (sub >> 1) * 4;
    const int brow = wc * 32 + rowin;
    const int bcol = (sub & 1) * 4;

    const int NIT = D_ / 32;
    issue(0, 0);
    issue(1, 32);
    int st = 0;
    for (int it = 0; it < NIT; ++it) {
        if (it + 1 < NIT) {
            cp_wait<1>();
        } else {
            cp_wait<0>();
        }
        __syncthreads();

        if (it + 2 < NIT) issue((st + 2) % 3, (it + 2) * 32);

        const unsigned aoff = sbase + st * (STAGE_FLOATS * 4);
        const unsigned boff = aoff + 128 * GSTRIDE * 4;

#pragma unroll
        for (int kk = 0; kk < 32; kk += 8) {
            unsigned af[4][4], bf[4][2];
#pragma unroll
            for (int mt = 0; mt < 4; ++mt)
                ldsm_x4(af[mt],
                        aoff + ((arow + mt * 16) * GSTRIDE + kk + acol) * 4);
#pragma unroll
            for (int nt = 0; nt < 4; ++nt)
                ldsm_x2(bf[nt],
                        boff + ((brow + nt * 8) * GSTRIDE + kk + bcol) * 4);
#pragma unroll
            for (int mt = 0; mt < 4; ++mt)
#pragma unroll
                for (int nt = 0; nt < 4; ++nt) mma_tf32(acc[mt][nt], af[mt], bf[nt]);
        }
        st = (st + 1) % 3;
    }

    // ---------------- Epilogue ----------------
#pragma unroll
    for (int mt = 0; mt < 4; ++mt) {
        int row0 = m0 + wr * 64 + mt * 16 + gid;
        int b0i = row0 >> 11, s0i = row0 & (S_ - 1);
        int row1 = row0 + 8;
        int b1i = row1 >> 11, s1i = row1 & (S_ - 1);

#pragma unroll
        for (int nt = 0; nt < 4; ++nt) {
            int col = n0 + wc * 32 + nt * 8 + 2 * tig;
            float e0 = acc[mt][nt][0], o0 = acc[mt][nt][1];
            float e1 = acc[mt][nt][2], o1 = acc[mt][nt][3];

            if (MODE == 2) {
                int j = (col & 63) >> 1;
                float2 cs0 = g_rope[(size_t)(b0i * S_ + s0i) * 32 + j];
                float2 cs1 = g_rope[(size_t)(b1i * S_ + s1i) * 32 + j];
                float re0 = e0 * cs0.x - o0 * cs0.y;
                float ro0 = e0 * cs0.y + o0 * cs0.x;
                float re1 = e1 * cs1.x - o1 * cs1.y;
                float ro1 = e1 * cs1.y + o1 * cs1.x;
                e0 = re0; o0 = ro0; e1 = re1; o1 = ro1;
            }

            if (MODE == 0) {
                *reinterpret_cast<float2*>(Cout + (size_t)row0 * D_ + col) =
                    make_float2(e0, o0);
                *reinterpret_cast<float2*>(Cout + (size_t)row1 * D_ + col) =
                    make_float2(e1, o1);
            } else {
                int h = col >> 6;
                int d = col & 63;
                *reinterpret_cast<float2*>(
                    Cout + (((size_t)(b0i * H_ + h) * S_ + s0i) * DK_ + d)) =
                    make_float2(tf32r(e0), tf32r(o0));
                *reinterpret_cast<float2*>(
                    Cout + (((size_t)(b1i * H_ + h) * S_ + s1i) * DK_ + d)) =
                    make_float2(tf32r(e1), tf32r(o1));
            }
        }
    }
}

__global__ void __launch_bounds__(256, 2) gemm_qkv_kernel(
    float* __restrict__ qp, float* __restrict__ kp, float* __restrict__ vp) {
    extern __shared__ float sm[];
    const int z = blockIdx.z;
    if (z == 0)      gemm_body<2>(sm, g_xf, g_wf, qp);
    else if (z == 1) gemm_body<2>(sm, g_xf, g_wf + (size_t)D_ * D_, kp);
    else             gemm_body<1>(sm, g_xf, g_wf + (size_t)2 * D_ * D_, vp);
}

__global__ void __launch_bounds__(256, 2) gemm_out_kernel(
    const float* __restrict__ A, float* __restrict__ Cout) {
    extern __shared__ float sm[];
    gemm_body<0>(sm, A, g_wf + (size_t)3 * D_ * D_, Cout);
}

// ---------------------------------------------------------------------------
// Flash attention, tf32 tensor cores, causal. BM=64/CTA, 128 threads
// (4 warps x 16 rows), 2 CTAs/SM. All operands on the tf32 grid; fragments
// gathered with ldmatrix (Q, K, P); V stays scalar (transposed access,
// conflict-free).
// ---------------------------------------------------------------------------
#define FP 68
#define VP 72
#define FLASH_SMEM ((64 * FP + 2 * 64 * FP + 2 * 64 * VP + 64 * FP) * 4)

__global__ void __launch_bounds__(128, 2) flash_tf32_kernel() {
    extern __shared__ float smf[];
    float* Qs = smf;                            // [64][FP]
    float* Ks = Qs + 64 * FP;                   // [2][64][FP]
    float* Vs = Ks + 2 * 64 * FP;               // [2][64][VP]
    float* Ps = Vs + 2 * 64 * VP;               // [64][FP] (tf32-grid P)

    const int qb = gridDim.x - 1 - blockIdx.x;  // long blocks first
    const int bh = blockIdx.y;
    const int b = bh >> 4;
    const int h = bh & 15;

    const float* Qp = g_q + (size_t)bh * S_ * DK_;
    const float* Kp = g_k + (size_t)bh * S_ * DK_;
    const float* Vp = g_v + (size_t)bh * S_ * DK_;

    const int tid = threadIdx.x;
    const int lane = tid & 31;
    const int warp = tid >> 5;                  // 0..3
    const int gid = lane >> 2;
    const int tig = lane & 3;
    const int sub = lane >> 3;                  // ldmatrix tile index
    const int rowin = lane & 7;
    const int q0 = qb * 64;
    const int mrow = warp * 16 + gid;           // 0..63

    const unsigned sbase = (unsigned)__cvta_generic_to_shared(smf);
    // A-frag gather bases (bytes): rows warp*16 + (sub&1)*8 + rowin, col (sub>>1)*4
    const unsigned qfrag =
        sbase + ((warp * 16 + (sub & 1) * 8 + rowin) * FP + (sub >> 1) * 4) * 4;
    const unsigned pfrag = qfrag + (64 * FP + 2 * 64 * FP + 2 * 64 * VP) * 4;
    // K-frag gather base: pair n2 covers rows 16*n2 + (sub>>1)*8 + rowin, col (sub&1)*4
    const unsigned kfrag0 =
        sbase + (64 * FP) * 4 +
        (((sub >> 1) * 8 + rowin) * FP + (sub & 1) * 4) * 4;

    // Load Q tile: x 0.125 (exact on tf32-grid values -> stays on grid).
#pragma unroll
    for (int i = 0; i < 8; ++i) {
        int l = tid + i * 128;
        int r = l >> 4;
        int c = (l & 15) << 2;
        float4 v = *reinterpret_cast<const float4*>(Qp + (size_t)(q0 + r) * DK_ + c);
        Qs[r * FP + c + 0] = v.x * 0.125f;
        Qs[r * FP + c + 1] = v.y * 0.125f;
        Qs[r * FP + c + 2] = v.z * 0.125f;
        Qs[r * FP + c + 3] = v.w * 0.125f;
    }

    auto issueKV = [&](int bf, int k0) {
#pragma unroll
        for (int i = 0; i < 8; ++i) {
            int l = tid + i * 128;
            int r = l >> 4;
            int c = (l & 15) << 2;
            cp_async16(Ks + bf * 64 * FP + r * FP + c,
                       Kp + (size_t)(k0 + r) * DK_ + c);
            cp_async16(Vs + bf * 64 * VP + r * VP + c,
                       Vp + (size_t)(k0 + r) * DK_ + c);
        }
        cp_commit();
    };

    issueKV(0, 0);

    float m_i[2] = {-1e30f, -1e30f};
    float l_i[2] = {0.f, 0.f};
    float Oacc[8][4];
#pragma unroll
    for (int nt = 0; nt < 8; ++nt)
#pragma unroll
        for (int r = 0; r < 4; ++r) Oacc[nt][r] = 0.0f;

    const int ntiles = qb + 1;
    int buf = 0;
    for (int kb = 0; kb < ntiles; ++kb) {
        const int k0 = kb * 64;
        cp_wait<0>();
        __syncthreads();
        if (kb + 1 < ntiles) issueKV(buf ^ 1, k0 + 64);

        // ---- S = Q K^T (ldmatrix-fed) ----
        const unsigned kfrag = kfrag0 + buf * (64 * FP * 4);
        float Sacc[8][4];
#pragma unroll
        for (int nt = 0; nt < 8; ++nt)
#pragma unroll
            for (int r = 0; r < 4; ++r) Sacc[nt][r] = 0.0f;

#pragma unroll
        for (int kk = 0; kk < 64; kk += 8) {
            unsigned af[4];
            ldsm_x4(af, qfrag + kk * 4);
#pragma unroll
            for (int n2 = 0; n2 < 4; ++n2) {
                unsigned kr[4];
                ldsm_x4(kr, kfrag + (n2 * 16 * FP + kk) * 4);
                mma_tf32b(Sacc[2 * n2], af, kr[0], kr[1]);
                mma_tf32b(Sacc[2 * n2 + 1], af, kr[2], kr[3]);
            }
        }

        // ---- causal mask ----
        const int row0 = q0 + mrow;
        const int row1 = row0 + 8;
        if (k0 + 63 > row0) {
#pragma unroll
            for (int nt = 0; nt < 8; ++nt) {
                int c0 = k0 + nt * 8 + 2 * tig;
                if (c0 > row0) Sacc[nt][0] = -1e30f;
                if (c0 + 1 > row0) Sacc[nt][1] = -1e30f;
                if (c0 > row1) Sacc[nt][2] = -1e30f;
                if (c0 + 1 > row1) Sacc[nt][3] = -1e30f;
            }
        }

        // ---- online softmax ----
        float mx0 = -1e30f, mx1 = -1e30f;
#pragma unroll
        for (int nt = 0; nt < 8; ++nt) {
            mx0 = fmaxf(mx0, fmaxf(Sacc[nt][0], Sacc[nt][1]));
            mx1 = fmaxf(mx1, fmaxf(Sacc[nt][2], Sacc[nt][3]));
        }
        mx0 = fmaxf(mx0, __shfl_xor_sync(0xffffffffu, mx0, 1));
        mx0 = fmaxf(mx0, __shfl_xor_sync(0xffffffffu, mx0, 2));
        mx1 = fmaxf(mx1, __shfl_xor_sync(0xffffffffu, mx1, 1));
        mx1 = fmaxf(mx1, __shfl_xor_sync(0xffffffffu, mx1, 2));

        float mn0 = fmaxf(m_i[0], mx0);
        float mn1 = fmaxf(m_i[1], mx1);
        float a0 = __expf(m_i[0] - mn0);
        float a1 = __expf(m_i[1] - mn1);

        float ps0 = 0.f, ps1 = 0.f;
#pragma unroll
        for (int nt = 0; nt < 8; ++nt) {
            float p00 = __expf(Sacc[nt][0] - mn0);
            float p01 = __expf(Sacc[nt][1] - mn0);
            float p10 = __expf(Sacc[nt][2] - mn1);
            float p11 = __expf(Sacc[nt][3] - mn1);
            ps0 += p00 + p01;
            ps1 += p10 + p11;
            // Store on the tf32 grid (PV reads raw; cvt@store == cvt@load).
            *reinterpret_cast<float2*>(&Ps[(mrow) * FP + nt * 8 + 2 * tig]) =
                make_float2(tf32r(p00), tf32r(p01));
            *reinterpret_cast<float2*>(&Ps[(mrow + 8) * FP + nt * 8 + 2 * tig]) =
                make_float2(tf32r(p10), tf32r(p11));
        }
        ps0 += __shfl_xor_sync(0xffffffffu, ps0, 1);
        ps0 += __shfl_xor_sync(0xffffffffu, ps0, 2);
        ps1 += __shfl_xor_sync(0xffffffffu, ps1, 1);
        ps1 += __shfl_xor_sync(0xffffffffu, ps1, 2);

        l_i[0] = l_i[0] * a0 + ps0;
        l_i[1] = l_i[1] * a1 + ps1;
        m_i[0] = mn0;
        m_i[1] = mn1;
#pragma unroll
        for (int nt = 0; nt < 8; ++nt) {
            Oacc[nt][0] *= a0;
            Oacc[nt][1] *= a0;
            Oacc[nt][2] *= a1;
            Oacc[nt][3] *= a1;
        }
        __syncwarp();   // P rows are warp-private

        // ---- O += P V (P via ldmatrix, V scalar conflict-free) ----
        const float* Vb = Vs + buf * 64 * VP;
#pragma unroll
        for (int kk = 0; kk < 64; kk += 8) {
            unsigned af[4];
            ldsm_x4(af, pfrag + kk * 4);
#pragma unroll
            for (int nt = 0; nt < 8; ++nt) {
                unsigned bf0 = __float_as_uint(Vb[(kk + tig) * VP + nt * 8 + gid]);
                unsigned bf1 =
                    __float_as_uint(Vb[(kk + tig + 4) * VP + nt * 8 + gid]);
                mma_tf32b(Oacc[nt], af, bf0, bf1);
            }
        }
        buf ^= 1;
    }

    // ---- normalize + write token-major (rounded to tf32 grid) ----
    float inv0 = 1.0f / l_i[0];
    float inv1 = 1.0f / l_i[1];
    const int row0 = q0 + mrow;
    const int row1 = row0 + 8;
#pragma unroll
    for (int nt = 0; nt < 8; ++nt) {
        int col = h * DK_ + nt * 8 + 2 * tig;
        *reinterpret_cast<float2*>(&g_attn[((size_t)(b * S_ + row0)) * D_ + col]) =
            make_float2(tf32r(Oacc[nt][0] * inv0), tf32r(Oacc[nt][1] * inv0));
        *reinterpret_cast<float2*>(&g_attn[((size_t)(b * S_ + row1)) * D_ + col]) =
            make_float2(tf32r(Oacc[nt][2] * inv1), tf32r(Oacc[nt][3] * inv1));
    }
}

// ---------------------------------------------------------------------------
extern "C" void kernel_launch(void* const* d_in, const int* in_sizes, int n_in,
                              void* d_out, int out_size) {
    const float* x = (const float*)d_in[0];
    const int* pos = (const int*)d_in[1];
    const float* wq = (const float*)d_in[2];
    const float* wk = (const float*)d_in[3];
    const float* wv = (const float*)d_in[4];
    const float* wo = (const float*)d_in[5];
    float* out = (float*)d_out;

    float *qp, *kp, *vp, *attnp;
    cudaGetSymbolAddress((void**)&qp, g_q);
    cudaGetSymbolAddress((void**)&kp, g_k);
    cudaGetSymbolAddress((void**)&vp, g_v);
    cudaGetSymbolAddress((void**)&attnp, g_attn);

    static bool attr_done = false;
    if (!attr_done) {
        cudaFuncSetAttribute(gemm_qkv_kernel,
                             cudaFuncAttributeMaxDynamicSharedMemorySize, GEMM_SMEM);
        cudaFuncSetAttribute(gemm_out_kernel,
                             cudaFuncAttributeMaxDynamicSharedMemorySize, GEMM_SMEM);
        cudaFuncSetAttribute(flash_tf32_kernel,
                             cudaFuncAttributeMaxDynamicSharedMemorySize, FLASH_SMEM);
        attr_done = true;
    }

    // Prep: tf32-round x and weights; RoPE cos/sin table.
    dim3 cvt_grid(M_ * D_ / 4 / 256, 5);
    cvt_tf32_kernel<<<cvt_grid, 256>>>(x, wq, wk, wv, wo);
    rope_table_kernel<<<(B_ * S_ * 32) / 256, 256>>>(pos);

    dim3 qkv_grid(D_ / 128, M_ / 128, 3);   // (8, 32, 3)
    gemm_qkv_kernel<<<qkv_grid, 256, GEMM_SMEM>>>(qp, kp, vp);

    dim3 flash_grid(S_ / 64, B_ * H_);      // (32, 32)
    flash_tf32_kernel<<<flash_grid, 128, FLASH_SMEM>>>();

    dim3 gemm_grid(D_ / 128, M_ / 128);     // (8, 32)
    gemm_out_kernel<<<gemm_grid, 256, GEMM_SMEM>>>(attnp, out);
}